// round 2
// baseline (speedup 1.0000x reference)
#include <cuda_runtime.h>
#include <mma.h>
#include <math.h>

using namespace nvcuda;

// Problem dims
#define BB 16
#define NN 1024
#define LL 313
#define CC 768
#define HH 12
#define DHD 64
#define TT (NN + LL)       // 1337
#define TPAD 1344          // 21 * 64
#define MLPD 3072

// ---------------- scratch (device globals; no allocations allowed) ----------
__device__ float g_xn[(size_t)BB * NN * CC];
__device__ float g_tokens[(size_t)BB * TT * CC];
__device__ float g_q[(size_t)BB * NN * CC];
__device__ float g_k[(size_t)BB * TT * CC];
__device__ float g_v[(size_t)BB * TT * CC];
__device__ float g_attn[(size_t)BB * NN * CC];
__device__ float g_x1[(size_t)BB * NN * CC];
__device__ float g_h2[(size_t)BB * NN * CC];
__device__ float g_act[(size_t)BB * NN * MLPD];

// ---------------- LayerNorm 1 + concat(color_emb) ---------------------------
// grid: B*T blocks, 256 threads. Rows t<N: LN(x) -> g_xn and g_tokens.
// Rows t>=N: copy color_emb -> g_tokens.
__global__ void ln1_concat_kernel(const float* __restrict__ x,
                                  const float* __restrict__ ce,
                                  const float* __restrict__ gam,
                                  const float* __restrict__ bet)
{
    int row = blockIdx.x;
    int b = row / TT;
    int t = row - b * TT;
    int tid = threadIdx.x;

    if (t >= NN) {
        const float* src = ce + ((size_t)b * LL + (t - NN)) * CC;
        float* dst = g_tokens + (size_t)row * CC;
        for (int i = tid; i < CC; i += 256) dst[i] = src[i];
        return;
    }

    const float* src = x + ((size_t)b * NN + t) * CC;
    float v0 = src[tid], v1 = src[tid + 256], v2 = src[tid + 512];
    float s = v0 + v1 + v2;
    float s2 = v0 * v0 + v1 * v1 + v2 * v2;

    __shared__ float rs[8], rs2[8];
    int lane = tid & 31, warp = tid >> 5;
    #pragma unroll
    for (int o = 16; o; o >>= 1) {
        s  += __shfl_xor_sync(~0u, s, o);
        s2 += __shfl_xor_sync(~0u, s2, o);
    }
    if (lane == 0) { rs[warp] = s; rs2[warp] = s2; }
    __syncthreads();
    if (tid == 0) {
        float a = 0.f, c = 0.f;
        #pragma unroll
        for (int i = 0; i < 8; i++) { a += rs[i]; c += rs2[i]; }
        rs[0] = a; rs2[0] = c;
    }
    __syncthreads();
    float mu = rs[0] * (1.0f / CC);
    float var = rs2[0] * (1.0f / CC) - mu * mu;
    float rstd = rsqrtf(var + 1e-5f);

    float* oxn = g_xn + ((size_t)b * NN + t) * CC;
    float* otk = g_tokens + (size_t)row * CC;
    int i = tid;
    float o = (v0 - mu) * rstd * gam[i] + bet[i]; oxn[i] = o; otk[i] = o;
    i = tid + 256;
    o = (v1 - mu) * rstd * gam[i] + bet[i]; oxn[i] = o; otk[i] = o;
    i = tid + 512;
    o = (v2 - mu) * rstd * gam[i] + bet[i]; oxn[i] = o; otk[i] = o;
}

// ---------------- LayerNorm 2 (x1 -> h2) ------------------------------------
__global__ void ln2_kernel(const float* __restrict__ gam,
                           const float* __restrict__ bet)
{
    int row = blockIdx.x;  // 0 .. B*N-1
    int tid = threadIdx.x;
    const float* src = g_x1 + (size_t)row * CC;
    float v0 = src[tid], v1 = src[tid + 256], v2 = src[tid + 512];
    float s = v0 + v1 + v2;
    float s2 = v0 * v0 + v1 * v1 + v2 * v2;

    __shared__ float rs[8], rs2[8];
    int lane = tid & 31, warp = tid >> 5;
    #pragma unroll
    for (int o = 16; o; o >>= 1) {
        s  += __shfl_xor_sync(~0u, s, o);
        s2 += __shfl_xor_sync(~0u, s2, o);
    }
    if (lane == 0) { rs[warp] = s; rs2[warp] = s2; }
    __syncthreads();
    if (tid == 0) {
        float a = 0.f, c = 0.f;
        #pragma unroll
        for (int i = 0; i < 8; i++) { a += rs[i]; c += rs2[i]; }
        rs[0] = a; rs2[0] = c;
    }
    __syncthreads();
    float mu = rs[0] * (1.0f / CC);
    float var = rs2[0] * (1.0f / CC) - mu * mu;
    float rstd = rsqrtf(var + 1e-5f);

    float* dst = g_h2 + (size_t)row * CC;
    int i = tid;
    dst[i] = (v0 - mu) * rstd * gam[i] + bet[i];
    i = tid + 256;
    dst[i] = (v1 - mu) * rstd * gam[i] + bet[i];
    i = tid + 512;
    dst[i] = (v2 - mu) * rstd * gam[i] + bet[i];
}

// ---------------- Generic tf32 WMMA GEMM ------------------------------------
// out[M,N] = epilogue(A[M,K] @ W[K,N] + bias[N])
// epi: 0 = bias only, 1 = bias + exact GELU, 2 = bias + residual add (res[M,N])
#define GBM 128
#define GBN 128
#define GBK 32
#define LDA_ 36
#define LDB_ 132
#define LDS_ 132
#define EPI_BIAS 0
#define EPI_GELU 1
#define EPI_ADD  2

__global__ void __launch_bounds__(256)
gemm_tf32_kernel(const float* __restrict__ A, const float* __restrict__ W,
                 const float* __restrict__ bias, const float* __restrict__ res,
                 float* __restrict__ out, int M, int N, int K, int epi)
{
    extern __shared__ float sm[];
    float* sA = sm;                  // [GBM][LDA_]
    float* sB = sm + GBM * LDA_;     // [GBK][LDB_]

    int m0 = blockIdx.x * GBM;
    int n0 = blockIdx.y * GBN;
    int tid = threadIdx.x;
    int warp = tid >> 5;
    int wm = warp >> 2;   // 0..1 : 64-row group
    int wn = warp & 3;    // 0..3 : 32-col group

    wmma::fragment<wmma::accumulator, 16, 16, 8, float> acc[4][2];
    #pragma unroll
    for (int i = 0; i < 4; i++)
        #pragma unroll
        for (int j = 0; j < 2; j++)
            wmma::fill_fragment(acc[i][j], 0.0f);

    for (int k0 = 0; k0 < K; k0 += GBK) {
        #pragma unroll
        for (int j = 0; j < 4; j++) {
            int f4 = tid + j * 256;        // 0..1023
            int r = f4 >> 3, c4 = f4 & 7;  // 128 rows x 8 float4
            float4 v = make_float4(0.f, 0.f, 0.f, 0.f);
            if (m0 + r < M)
                v = *(const float4*)(A + (size_t)(m0 + r) * K + k0 + c4 * 4);
            *(float4*)(sA + r * LDA_ + c4 * 4) = v;
        }
        #pragma unroll
        for (int j = 0; j < 4; j++) {
            int f4 = tid + j * 256;
            int r = f4 >> 5, c4 = f4 & 31; // 32 rows x 32 float4
            float4 v = *(const float4*)(W + (size_t)(k0 + r) * N + n0 + c4 * 4);
            *(float4*)(sB + r * LDB_ + c4 * 4) = v;
        }
        __syncthreads();

        #pragma unroll
        for (int kk = 0; kk < GBK; kk += 8) {
            wmma::fragment<wmma::matrix_a, 16, 16, 8, wmma::precision::tf32, wmma::row_major> af[4];
            wmma::fragment<wmma::matrix_b, 16, 16, 8, wmma::precision::tf32, wmma::row_major> bf[2];
            #pragma unroll
            for (int i = 0; i < 4; i++) {
                wmma::load_matrix_sync(af[i], sA + (wm * 64 + i * 16) * LDA_ + kk, LDA_);
                #pragma unroll
                for (int e = 0; e < af[i].num_elements; e++)
                    af[i].x[e] = wmma::__float_to_tf32(af[i].x[e]);
            }
            #pragma unroll
            for (int j = 0; j < 2; j++) {
                wmma::load_matrix_sync(bf[j], sB + kk * LDB_ + wn * 32 + j * 16, LDB_);
                #pragma unroll
                for (int e = 0; e < bf[j].num_elements; e++)
                    bf[j].x[e] = wmma::__float_to_tf32(bf[j].x[e]);
            }
            #pragma unroll
            for (int i = 0; i < 4; i++)
                #pragma unroll
                for (int j = 0; j < 2; j++)
                    wmma::mma_sync(acc[i][j], af[i], bf[j], acc[i][j]);
        }
        __syncthreads();
    }

    // Epilogue via smem staging (reuses tile smem)
    float* stage = sm;
    #pragma unroll
    for (int i = 0; i < 4; i++)
        #pragma unroll
        for (int j = 0; j < 2; j++)
            wmma::store_matrix_sync(stage + (wm * 64 + i * 16) * LDS_ + wn * 32 + j * 16,
                                    acc[i][j], LDS_, wmma::mem_row_major);
    __syncthreads();

    for (int e = tid; e < GBM * GBN; e += 256) {
        int r = e >> 7, c = e & 127;
        int gr = m0 + r, gc = n0 + c;
        if (gr < M) {
            float v = stage[r * LDS_ + c] + bias[gc];
            if (epi == EPI_GELU)
                v = 0.5f * v * (1.0f + erff(v * 0.70710678118654752f));
            else if (epi == EPI_ADD)
                v += res[(size_t)gr * N + gc];
            out[(size_t)gr * N + gc] = v;
        }
    }
}

// ---------------- Attention (full score row in smem) -------------------------
// grid: (N/32, H, B), 256 threads. smem: Q 32x64 | KV 64x64 | S 32x1344.
__global__ void __launch_bounds__(256)
attn_kernel(const int* __restrict__ mask)
{
    extern __shared__ float sm[];
    float* sQ  = sm;                    // 2048
    float* sKV = sm + 32 * 64;          // 4096
    float* sS  = sKV + 64 * 64;         // 32 * TPAD

    int q0 = blockIdx.x * 32;
    int h = blockIdx.y;
    int b = blockIdx.z;
    int tid = threadIdx.x;
    int warp = tid >> 5, lane = tid & 31;
    int wr = warp >> 2;   // 0..1 : 16-row group of the 32-query tile
    int wc = warp & 3;    // 0..3 : 16-col group

    // Load Q tile, pre-scaled by DH^-0.5 = 0.125
    {
        const float* qb = g_q + ((size_t)b * NN + q0) * CC + h * DHD;
        #pragma unroll
        for (int j = 0; j < 2; j++) {
            int f4 = tid + j * 256;          // 0..511
            int r = f4 >> 4, c4 = f4 & 15;   // 32 rows x 16 float4
            float4 v = *(const float4*)(qb + (size_t)r * CC + c4 * 4);
            v.x *= 0.125f; v.y *= 0.125f; v.z *= 0.125f; v.w *= 0.125f;
            *(float4*)(sQ + r * 64 + c4 * 4) = v;
        }
    }

    // Phase 1: S = Qs @ K^T over all key chunks
    const float* kb = g_k + (size_t)b * TT * CC + h * DHD;
    for (int t0 = 0; t0 < TPAD; t0 += 64) {
        __syncthreads();
        #pragma unroll
        for (int j = 0; j < 4; j++) {
            int f4 = tid + j * 256;          // 0..1023
            int r = f4 >> 4, c4 = f4 & 15;   // 64 rows x 16 float4
            float4 v = make_float4(0.f, 0.f, 0.f, 0.f);
            if (t0 + r < TT)
                v = *(const float4*)(kb + (size_t)(t0 + r) * CC + c4 * 4);
            *(float4*)(sKV + r * 64 + c4 * 4) = v;
        }
        __syncthreads();

        wmma::fragment<wmma::accumulator, 16, 16, 8, float> s_acc;
        wmma::fill_fragment(s_acc, 0.0f);
        #pragma unroll
        for (int kk = 0; kk < DHD; kk += 8) {
            wmma::fragment<wmma::matrix_a, 16, 16, 8, wmma::precision::tf32, wmma::row_major> af;
            wmma::fragment<wmma::matrix_b, 16, 16, 8, wmma::precision::tf32, wmma::col_major> bf;
            wmma::load_matrix_sync(af, sQ + (wr * 16) * 64 + kk, 64);
            #pragma unroll
            for (int e = 0; e < af.num_elements; e++)
                af.x[e] = wmma::__float_to_tf32(af.x[e]);
            wmma::load_matrix_sync(bf, sKV + (wc * 16) * 64 + kk, 64);
            #pragma unroll
            for (int e = 0; e < bf.num_elements; e++)
                bf.x[e] = wmma::__float_to_tf32(bf.x[e]);
            wmma::mma_sync(s_acc, af, bf, s_acc);
        }
        wmma::store_matrix_sync(sS + (wr * 16) * TPAD + t0 + wc * 16, s_acc,
                                TPAD, wmma::mem_row_major);
    }
    __syncthreads();

    // Phase 2: mask + softmax, warp w owns rows w*4 .. w*4+3
    #pragma unroll
    for (int k = 0; k < 4; k++) {
        int r = warp * 4 + k;
        float* srow = sS + (size_t)r * TPAD;
        const int* mrow = mask + ((size_t)b * NN + q0 + r) * TT;
        float m = -INFINITY;
        for (int c = lane; c < TPAD; c += 32) {
            float sval = -INFINITY;
            if (c < TT && mrow[c] != 0) sval = srow[c];
            srow[c] = sval;
            m = fmaxf(m, sval);
        }
        #pragma unroll
        for (int o = 16; o; o >>= 1) m = fmaxf(m, __shfl_xor_sync(~0u, m, o));
        float sum = 0.f;
        for (int c = lane; c < TPAD; c += 32) {
            float p = __expf(srow[c] - m);
            srow[c] = p;
            sum += p;
        }
        #pragma unroll
        for (int o = 16; o; o >>= 1) sum += __shfl_xor_sync(~0u, sum, o);
        float inv = 1.0f / sum;
        for (int c = lane; c < TPAD; c += 32) srow[c] *= inv;
    }
    __syncthreads();

    // Phase 3: O = P @ V
    const float* vb = g_v + (size_t)b * TT * CC + h * DHD;
    wmma::fragment<wmma::accumulator, 16, 16, 8, float> o_acc;
    wmma::fill_fragment(o_acc, 0.0f);
    for (int t0 = 0; t0 < TPAD; t0 += 64) {
        __syncthreads();
        #pragma unroll
        for (int j = 0; j < 4; j++) {
            int f4 = tid + j * 256;
            int r = f4 >> 4, c4 = f4 & 15;
            float4 v = make_float4(0.f, 0.f, 0.f, 0.f);
            if (t0 + r < TT)
                v = *(const float4*)(vb + (size_t)(t0 + r) * CC + c4 * 4);
            *(float4*)(sKV + r * 64 + c4 * 4) = v;
        }
        __syncthreads();

        #pragma unroll
        for (int kk = 0; kk < 64; kk += 8) {
            wmma::fragment<wmma::matrix_a, 16, 16, 8, wmma::precision::tf32, wmma::row_major> af;
            wmma::fragment<wmma::matrix_b, 16, 16, 8, wmma::precision::tf32, wmma::row_major> bf;
            wmma::load_matrix_sync(af, sS + (wr * 16) * TPAD + t0 + kk, TPAD);
            #pragma unroll
            for (int e = 0; e < af.num_elements; e++)
                af.x[e] = wmma::__float_to_tf32(af.x[e]);
            wmma::load_matrix_sync(bf, sKV + kk * 64 + wc * 16, 64);
            #pragma unroll
            for (int e = 0; e < bf.num_elements; e++)
                bf.x[e] = wmma::__float_to_tf32(bf.x[e]);
            wmma::mma_sync(o_acc, af, bf, o_acc);
        }
    }

    float* ob = g_attn + ((size_t)b * NN + q0 + wr * 16) * CC + h * DHD + wc * 16;
    wmma::store_matrix_sync(ob, o_acc, CC, wmma::mem_row_major);
}

// ---------------- launch -----------------------------------------------------
extern "C" void kernel_launch(void* const* d_in, const int* in_sizes, int n_in,
                              void* d_out, int out_size)
{
    const float* x    = (const float*)d_in[0];
    const float* ce   = (const float*)d_in[1];
    const int*   mask = (const int*)  d_in[2];
    const float* ln1g = (const float*)d_in[3];
    const float* ln1b = (const float*)d_in[4];
    const float* ln2g = (const float*)d_in[5];
    const float* ln2b = (const float*)d_in[6];
    const float* Wq   = (const float*)d_in[7];
    const float* bq   = (const float*)d_in[8];
    const float* Wk   = (const float*)d_in[9];
    const float* bk   = (const float*)d_in[10];
    const float* Wv   = (const float*)d_in[11];
    const float* bv   = (const float*)d_in[12];
    const float* Wp   = (const float*)d_in[13];
    const float* bp   = (const float*)d_in[14];
    const float* W1   = (const float*)d_in[15];
    const float* b1   = (const float*)d_in[16];
    const float* W2   = (const float*)d_in[17];
    const float* b2   = (const float*)d_in[18];
    float* out = (float*)d_out;

    float *p_xn, *p_tok, *p_q, *p_k, *p_v, *p_attn, *p_x1, *p_h2, *p_act;
    cudaGetSymbolAddress((void**)&p_xn,   g_xn);
    cudaGetSymbolAddress((void**)&p_tok,  g_tokens);
    cudaGetSymbolAddress((void**)&p_q,    g_q);
    cudaGetSymbolAddress((void**)&p_k,    g_k);
    cudaGetSymbolAddress((void**)&p_v,    g_v);
    cudaGetSymbolAddress((void**)&p_attn, g_attn);
    cudaGetSymbolAddress((void**)&p_x1,   g_x1);
    cudaGetSymbolAddress((void**)&p_h2,   g_h2);
    cudaGetSymbolAddress((void**)&p_act,  g_act);

    const size_t gemm_smem = (size_t)GBM * LDS_ * sizeof(float);                 // 67584
    const size_t attn_smem = (size_t)(32 * 64 + 64 * 64 + 32 * TPAD) * sizeof(float); // 196608
    cudaFuncSetAttribute(gemm_tf32_kernel, cudaFuncAttributeMaxDynamicSharedMemorySize, (int)gemm_smem);
    cudaFuncSetAttribute(attn_kernel, cudaFuncAttributeMaxDynamicSharedMemorySize, (int)attn_smem);

    // 1. LN1 + concat tokens
    ln1_concat_kernel<<<BB * TT, 256>>>(x, ce, ln1g, ln1b);

    // 2. Q/K/V projections
    dim3 gq((BB * NN + GBM - 1) / GBM, CC / GBN);   // (128, 6)
    dim3 gkv((BB * TT + GBM - 1) / GBM, CC / GBN);  // (168, 6)
    gemm_tf32_kernel<<<gq, 256, gemm_smem>>>(p_xn,  Wq, bq, nullptr, p_q, BB * NN, CC, CC, EPI_BIAS);
    gemm_tf32_kernel<<<gkv, 256, gemm_smem>>>(p_tok, Wk, bk, nullptr, p_k, BB * TT, CC, CC, EPI_BIAS);
    gemm_tf32_kernel<<<gkv, 256, gemm_smem>>>(p_tok, Wv, bv, nullptr, p_v, BB * TT, CC, CC, EPI_BIAS);

    // 3. Attention
    attn_kernel<<<dim3(NN / 32, HH, BB), 256, attn_smem>>>(mask);

    // 4. Output projection + residual (x1 = xn + attn_out @ Wp + bp)
    gemm_tf32_kernel<<<gq, 256, gemm_smem>>>(p_attn, Wp, bp, p_xn, p_x1, BB * NN, CC, CC, EPI_ADD);

    // 5. LN2
    ln2_kernel<<<BB * NN, 256>>>(ln2g, ln2b);

    // 6. MLP
    dim3 g1((BB * NN + GBM - 1) / GBM, MLPD / GBN); // (128, 24)
    gemm_tf32_kernel<<<g1, 256, gemm_smem>>>(p_h2, W1, b1, nullptr, p_act, BB * NN, MLPD, CC, EPI_GELU);
    gemm_tf32_kernel<<<gq, 256, gemm_smem>>>(p_act, W2, b2, p_x1, out, BB * NN, CC, MLPD, EPI_ADD);
}

// round 4
// speedup vs baseline: 2.8896x; 2.8896x over previous
#include <cuda_runtime.h>
#include <mma.h>
#include <math.h>

using namespace nvcuda;

// Problem dims
#define BB 16
#define NN 1024
#define LL 313
#define CC 768
#define HH 12
#define DHD 64
#define TT (NN + LL)       // 1337
#define TPAD 1344          // 21 * 64
#define MLPD 3072
#define NW 42              // TPAD/32 mask words per row

// ---------------- scratch (device globals; no allocations allowed) ----------
__device__ float g_xn[(size_t)BB * NN * CC];
__device__ float g_tokens[(size_t)BB * TT * CC];
__device__ float g_q[(size_t)BB * NN * CC];
__device__ float g_k[(size_t)BB * TT * CC];
__device__ float g_v[(size_t)BB * TT * CC];
__device__ float g_attn[(size_t)BB * NN * CC];
__device__ float g_x1[(size_t)BB * NN * CC];
__device__ float g_h2[(size_t)BB * NN * CC];
__device__ float g_act[(size_t)BB * NN * MLPD];
__device__ unsigned g_mbits[(size_t)BB * NN * NW];

// ---------------- cp.async helpers ------------------------------------------
__device__ __forceinline__ void cp_async16(float* dst, const float* src) {
    unsigned s = (unsigned)__cvta_generic_to_shared(dst);
    asm volatile("cp.async.cg.shared.global [%0], [%1], 16;\n" :: "r"(s), "l"(src));
}
__device__ __forceinline__ void cp_async16_pred(float* dst, const float* src, bool p) {
    unsigned s = (unsigned)__cvta_generic_to_shared(dst);
    int bytes = p ? 16 : 0;
    asm volatile("cp.async.cg.shared.global [%0], [%1], 16, %2;\n" :: "r"(s), "l"(src), "r"(bytes));
}

// ---------------- mask bit-packing ------------------------------------------
// one warp per 32-col word; coalesced reads + ballot.
__global__ void mask_pack_kernel(const int* __restrict__ mask)
{
    int widx = blockIdx.x * 8 + (threadIdx.x >> 5);
    int lane = threadIdx.x & 31;
    if (widx >= BB * NN * NW) return;
    int w = widx % NW;
    int row = widx / NW;          // b*N + n
    int gc = w * 32 + lane;
    int mval = (gc < TT) ? mask[(size_t)row * TT + gc] : 0;
    unsigned bits = __ballot_sync(~0u, mval != 0);
    if (lane == 0) g_mbits[widx] = bits;
}

// ---------------- LayerNorm 1 + concat(color_emb) ---------------------------
__global__ void ln1_concat_kernel(const float* __restrict__ x,
                                  const float* __restrict__ ce,
                                  const float* __restrict__ gam,
                                  const float* __restrict__ bet)
{
    int row = blockIdx.x;
    int b = row / TT;
    int t = row - b * TT;
    int tid = threadIdx.x;

    if (t >= NN) {
        const float* src = ce + ((size_t)b * LL + (t - NN)) * CC;
        float* dst = g_tokens + (size_t)row * CC;
        for (int i = tid; i < CC; i += 256) dst[i] = src[i];
        return;
    }

    const float* src = x + ((size_t)b * NN + t) * CC;
    float v0 = src[tid], v1 = src[tid + 256], v2 = src[tid + 512];
    float s = v0 + v1 + v2;
    float s2 = v0 * v0 + v1 * v1 + v2 * v2;

    __shared__ float rs[8], rs2[8];
    int lane = tid & 31, warp = tid >> 5;
    #pragma unroll
    for (int o = 16; o; o >>= 1) {
        s  += __shfl_xor_sync(~0u, s, o);
        s2 += __shfl_xor_sync(~0u, s2, o);
    }
    if (lane == 0) { rs[warp] = s; rs2[warp] = s2; }
    __syncthreads();
    if (tid == 0) {
        float a = 0.f, c = 0.f;
        #pragma unroll
        for (int i = 0; i < 8; i++) { a += rs[i]; c += rs2[i]; }
        rs[0] = a; rs2[0] = c;
    }
    __syncthreads();
    float mu = rs[0] * (1.0f / CC);
    float var = rs2[0] * (1.0f / CC) - mu * mu;
    float rstd = rsqrtf(var + 1e-5f);

    float* oxn = g_xn + ((size_t)b * NN + t) * CC;
    float* otk = g_tokens + (size_t)row * CC;
    int i = tid;
    float o = (v0 - mu) * rstd * gam[i] + bet[i]; oxn[i] = o; otk[i] = o;
    i = tid + 256;
    o = (v1 - mu) * rstd * gam[i] + bet[i]; oxn[i] = o; otk[i] = o;
    i = tid + 512;
    o = (v2 - mu) * rstd * gam[i] + bet[i]; oxn[i] = o; otk[i] = o;
}

// ---------------- LayerNorm 2 (x1 -> h2) ------------------------------------
__global__ void ln2_kernel(const float* __restrict__ gam,
                           const float* __restrict__ bet)
{
    int row = blockIdx.x;
    int tid = threadIdx.x;
    const float* src = g_x1 + (size_t)row * CC;
    float v0 = src[tid], v1 = src[tid + 256], v2 = src[tid + 512];
    float s = v0 + v1 + v2;
    float s2 = v0 * v0 + v1 * v1 + v2 * v2;

    __shared__ float rs[8], rs2[8];
    int lane = tid & 31, warp = tid >> 5;
    #pragma unroll
    for (int o = 16; o; o >>= 1) {
        s  += __shfl_xor_sync(~0u, s, o);
        s2 += __shfl_xor_sync(~0u, s2, o);
    }
    if (lane == 0) { rs[warp] = s; rs2[warp] = s2; }
    __syncthreads();
    if (tid == 0) {
        float a = 0.f, c = 0.f;
        #pragma unroll
        for (int i = 0; i < 8; i++) { a += rs[i]; c += rs2[i]; }
        rs[0] = a; rs2[0] = c;
    }
    __syncthreads();
    float mu = rs[0] * (1.0f / CC);
    float var = rs2[0] * (1.0f / CC) - mu * mu;
    float rstd = rsqrtf(var + 1e-5f);

    float* dst = g_h2 + (size_t)row * CC;
    int i = tid;
    dst[i] = (v0 - mu) * rstd * gam[i] + bet[i];
    i = tid + 256;
    dst[i] = (v1 - mu) * rstd * gam[i] + bet[i];
    i = tid + 512;
    dst[i] = (v2 - mu) * rstd * gam[i] + bet[i];
}

// ---------------- tf32 WMMA GEMM, cp.async double-buffered -------------------
#define GBM 128
#define GBN 128
#define GBK 32
#define LDA_ 36
#define LDB_ 132
#define LDS_ 132
#define STG_ (GBM * LDA_ + GBK * LDB_)   // 8832 floats per stage
#define EPI_BIAS 0
#define EPI_GELU 1
#define EPI_ADD  2

__global__ void __launch_bounds__(256, 2)
gemm_tf32_kernel(const float* __restrict__ A, const float* __restrict__ W,
                 const float* __restrict__ bias, const float* __restrict__ res,
                 float* __restrict__ out, int M, int N, int K, int epi)
{
    extern __shared__ float sm[];
    int m0 = blockIdx.x * GBM;
    int n0 = blockIdx.y * GBN;
    int tid = threadIdx.x;
    int warp = tid >> 5;
    int wm = warp >> 2;   // 0..1
    int wn = warp & 3;    // 0..3

    wmma::fragment<wmma::accumulator, 16, 16, 8, float> acc[4][2];
    #pragma unroll
    for (int i = 0; i < 4; i++)
        #pragma unroll
        for (int j = 0; j < 2; j++)
            wmma::fill_fragment(acc[i][j], 0.0f);

    // per-thread load coords
    int ar = 0, ac4 = 0, br = 0, bc4 = 0;
    ar = tid >> 3; ac4 = tid & 7;        // base; j adds 32 rows for A
    br = tid >> 5; bc4 = tid & 31;       // j adds 8 rows for B

    auto load_stage = [&](int k0, int s) {
        float* sA = sm + s * STG_;
        float* sB = sA + GBM * LDA_;
        #pragma unroll
        for (int j = 0; j < 4; j++) {
            int r = ar + j * 32;
            int gr = m0 + r;
            const float* src = A + (size_t)(gr < M ? gr : M - 1) * K + k0 + ac4 * 4;
            cp_async16_pred(sA + r * LDA_ + ac4 * 4, src, gr < M);
        }
        #pragma unroll
        for (int j = 0; j < 4; j++) {
            int r = br + j * 8;
            const float* src = W + (size_t)(k0 + r) * N + n0 + bc4 * 4;
            cp_async16(sB + r * LDB_ + bc4 * 4, src);
        }
        asm volatile("cp.async.commit_group;\n");
    };

    int KT = K / GBK;
    load_stage(0, 0);

    for (int kt = 0; kt < KT; kt++) {
        if (kt + 1 < KT) load_stage((kt + 1) * GBK, (kt + 1) & 1);
        else asm volatile("cp.async.commit_group;\n");
        asm volatile("cp.async.wait_group 1;\n");
        __syncthreads();

        float* sA = sm + (kt & 1) * STG_;
        float* sB = sA + GBM * LDA_;
        #pragma unroll
        for (int kk = 0; kk < GBK; kk += 8) {
            wmma::fragment<wmma::matrix_a, 16, 16, 8, wmma::precision::tf32, wmma::row_major> af[4];
            wmma::fragment<wmma::matrix_b, 16, 16, 8, wmma::precision::tf32, wmma::row_major> bf[2];
            #pragma unroll
            for (int i = 0; i < 4; i++)
                wmma::load_matrix_sync(af[i], sA + (wm * 64 + i * 16) * LDA_ + kk, LDA_);
            #pragma unroll
            for (int j = 0; j < 2; j++)
                wmma::load_matrix_sync(bf[j], sB + kk * LDB_ + wn * 32 + j * 16, LDB_);
            #pragma unroll
            for (int i = 0; i < 4; i++)
                #pragma unroll
                for (int j = 0; j < 2; j++)
                    wmma::mma_sync(acc[i][j], af[i], bf[j], acc[i][j]);
        }
        __syncthreads();
    }

    // Epilogue via smem staging (reuses tile smem)
    float* stage = sm;
    #pragma unroll
    for (int i = 0; i < 4; i++)
        #pragma unroll
        for (int j = 0; j < 2; j++)
            wmma::store_matrix_sync(stage + (wm * 64 + i * 16) * LDS_ + wn * 32 + j * 16,
                                    acc[i][j], LDS_, wmma::mem_row_major);
    __syncthreads();

    for (int e = tid; e < GBM * GBN; e += 256) {
        int r = e >> 7, c = e & 127;
        int gr = m0 + r, gc = n0 + c;
        if (gr < M) {
            float v = stage[r * LDS_ + c] + bias[gc];
            if (epi == EPI_GELU)
                v = 0.5f * v * (1.0f + erff(v * 0.70710678118654752f));
            else if (epi == EPI_ADD)
                v += res[(size_t)gr * N + gc];
            out[(size_t)gr * N + gc] = v;
        }
    }
}

// ---------------- Flash-style attention --------------------------------------
// grid (N/64, H, B), 256 threads (8 warps). Online softmax, O resident in smem.
#define AQ 64
#define LDH 68
// smem floats: Q | K | V | P | O | Stage (each 64*68) + m/l/sf (64 each)
#define A_Q   0
#define A_K   (64 * LDH)
#define A_V   (2 * 64 * LDH)
#define A_P   (3 * 64 * LDH)
#define A_O   (4 * 64 * LDH)
#define A_ST  (5 * 64 * LDH)
#define A_M   (6 * 64 * LDH)
#define A_L   (A_M + 64)
#define A_SF  (A_L + 64)
#define ATTN_SMEM_FLOATS (A_SF + 64)

__global__ void __launch_bounds__(256, 2)
attn_kernel()
{
    extern __shared__ float sm[];
    int q0 = blockIdx.x * AQ;
    int h = blockIdx.y;
    int b = blockIdx.z;
    int tid = threadIdx.x;
    int warp = tid >> 5, lane = tid & 31;
    int wr = warp >> 1;   // 0..3 : 16-row group
    int wc = warp & 1;    // 0..1 : 32-col group

    // init stats + O
    if (tid < 64) { sm[A_M + tid] = -1e30f; sm[A_L + tid] = 0.f; }
    #pragma unroll
    for (int j = 0; j < 4; j++) {
        int e = tid + j * 256;          // 1024 float4
        int r = e >> 4, c4 = e & 15;
        *(float4*)(sm + A_O + r * LDH + c4 * 4) = make_float4(0.f, 0.f, 0.f, 0.f);
    }

    // load Q (scaled)
    {
        const float* qb = g_q + ((size_t)b * NN + q0) * CC + h * DHD;
        #pragma unroll
        for (int j = 0; j < 4; j++) {
            int e = tid + j * 256;
            int r = e >> 4, c4 = e & 15;
            float4 v = *(const float4*)(qb + (size_t)r * CC + c4 * 4);
            v.x *= 0.125f; v.y *= 0.125f; v.z *= 0.125f; v.w *= 0.125f;
            *(float4*)(sm + A_Q + r * LDH + c4 * 4) = v;
        }
    }

    const float* kb = g_k + (size_t)b * TT * CC + h * DHD;
    const float* vb = g_v + (size_t)b * TT * CC + h * DHD;
    const unsigned* mb = g_mbits + ((size_t)b * NN + q0) * NW;

    for (int t0 = 0; t0 < TPAD; t0 += 64) {
        // load K and V chunks (zero-pad past TT)
        #pragma unroll
        for (int j = 0; j < 8; j++) {
            int e = tid + j * 256;              // 0..2047
            int half = e >> 10;                 // 0=K, 1=V
            int ee = e & 1023;
            int r = ee >> 4, c4 = ee & 15;
            int row = t0 + r;
            float4 v = make_float4(0.f, 0.f, 0.f, 0.f);
            if (row < TT) {
                const float* src = (half ? vb : kb) + (size_t)row * CC + c4 * 4;
                v = *(const float4*)src;
            }
            *(float4*)(sm + (half ? A_V : A_K) + r * LDH + c4 * 4) = v;
        }
        __syncthreads();

        // S = Q @ K^T  (64x64)
        {
            wmma::fragment<wmma::accumulator, 16, 16, 8, float> sacc[2];
            wmma::fill_fragment(sacc[0], 0.0f);
            wmma::fill_fragment(sacc[1], 0.0f);
            #pragma unroll
            for (int kk = 0; kk < DHD; kk += 8) {
                wmma::fragment<wmma::matrix_a, 16, 16, 8, wmma::precision::tf32, wmma::row_major> af;
                wmma::fragment<wmma::matrix_b, 16, 16, 8, wmma::precision::tf32, wmma::col_major> bf;
                wmma::load_matrix_sync(af, sm + A_Q + (wr * 16) * LDH + kk, LDH);
                #pragma unroll
                for (int j = 0; j < 2; j++) {
                    wmma::load_matrix_sync(bf, sm + A_K + (wc * 32 + j * 16) * LDH + kk, LDH);
                    wmma::mma_sync(sacc[j], af, bf, sacc[j]);
                }
            }
            #pragma unroll
            for (int j = 0; j < 2; j++)
                wmma::store_matrix_sync(sm + A_P + (wr * 16) * LDH + wc * 32 + j * 16,
                                        sacc[j], LDH, wmma::mem_row_major);
        }
        __syncthreads();

        // online softmax: warp owns rows warp*8 .. +7
        #pragma unroll
        for (int i = 0; i < 8; i++) {
            int r = warp * 8 + i;
            float* prow = sm + A_P + r * LDH;
            unsigned w0 = mb[(size_t)r * NW + (t0 >> 5)];
            unsigned w1 = mb[(size_t)r * NW + (t0 >> 5) + 1];
            bool v0 = (w0 >> lane) & 1u;
            bool v1 = (w1 >> lane) & 1u;
            float x0 = v0 ? prow[lane] : -1e30f;
            float x1 = v1 ? prow[lane + 32] : -1e30f;
            float cm = fmaxf(x0, x1);
            #pragma unroll
            for (int o = 16; o; o >>= 1) cm = fmaxf(cm, __shfl_xor_sync(~0u, cm, o));
            float m_old = sm[A_M + r];
            float m_new = fmaxf(m_old, cm);
            float p0 = v0 ? __expf(x0 - m_new) : 0.f;
            float p1 = v1 ? __expf(x1 - m_new) : 0.f;
            float ps = p0 + p1;
            #pragma unroll
            for (int o = 16; o; o >>= 1) ps += __shfl_xor_sync(~0u, ps, o);
            prow[lane] = p0;
            prow[lane + 32] = p1;
            if (lane == 0) {
                float sf = __expf(m_old - m_new);
                sm[A_SF + r] = sf;
                sm[A_L + r] = sm[A_L + r] * sf + ps;
                sm[A_M + r] = m_new;
            }
        }
        __syncthreads();

        // PV chunk = P @ V  (64x64) -> stage
        {
            wmma::fragment<wmma::accumulator, 16, 16, 8, float> oacc[2];
            wmma::fill_fragment(oacc[0], 0.0f);
            wmma::fill_fragment(oacc[1], 0.0f);
            #pragma unroll
            for (int kk = 0; kk < 64; kk += 8) {
                wmma::fragment<wmma::matrix_a, 16, 16, 8, wmma::precision::tf32, wmma::row_major> af;
                wmma::fragment<wmma::matrix_b, 16, 16, 8, wmma::precision::tf32, wmma::row_major> bf;
                wmma::load_matrix_sync(af, sm + A_P + (wr * 16) * LDH + kk, LDH);
                #pragma unroll
                for (int j = 0; j < 2; j++) {
                    wmma::load_matrix_sync(bf, sm + A_V + kk * LDH + wc * 32 + j * 16, LDH);
                    wmma::mma_sync(oacc[j], af, bf, oacc[j]);
                }
            }
            #pragma unroll
            for (int j = 0; j < 2; j++)
                wmma::store_matrix_sync(sm + A_ST + (wr * 16) * LDH + wc * 32 + j * 16,
                                        oacc[j], LDH, wmma::mem_row_major);
        }
        __syncthreads();

        // O = O * sf + stage
        #pragma unroll
        for (int j = 0; j < 4; j++) {
            int e = tid + j * 256;
            int r = e >> 4, c4 = e & 15;
            float sf = sm[A_SF + r];
            float4 o = *(float4*)(sm + A_O + r * LDH + c4 * 4);
            float4 st = *(float4*)(sm + A_ST + r * LDH + c4 * 4);
            o.x = o.x * sf + st.x; o.y = o.y * sf + st.y;
            o.z = o.z * sf + st.z; o.w = o.w * sf + st.w;
            *(float4*)(sm + A_O + r * LDH + c4 * 4) = o;
        }
        __syncthreads();
    }

    // write O / l
    float* ob = g_attn + ((size_t)b * NN + q0) * CC + h * DHD;
    #pragma unroll
    for (int j = 0; j < 4; j++) {
        int e = tid + j * 256;
        int r = e >> 4, c4 = e & 15;
        float inv = 1.0f / sm[A_L + r];
        float4 o = *(float4*)(sm + A_O + r * LDH + c4 * 4);
        o.x *= inv; o.y *= inv; o.z *= inv; o.w *= inv;
        *(float4*)(ob + (size_t)r * CC + c4 * 4) = o;
    }
}

// ---------------- launch -----------------------------------------------------
extern "C" void kernel_launch(void* const* d_in, const int* in_sizes, int n_in,
                              void* d_out, int out_size)
{
    const float* x    = (const float*)d_in[0];
    const float* ce   = (const float*)d_in[1];
    const int*   mask = (const int*)  d_in[2];
    const float* ln1g = (const float*)d_in[3];
    const float* ln1b = (const float*)d_in[4];
    const float* ln2g = (const float*)d_in[5];
    const float* ln2b = (const float*)d_in[6];
    const float* Wq   = (const float*)d_in[7];
    const float* bq   = (const float*)d_in[8];
    const float* Wk   = (const float*)d_in[9];
    const float* bk   = (const float*)d_in[10];
    const float* Wv   = (const float*)d_in[11];
    const float* bv   = (const float*)d_in[12];
    const float* Wp   = (const float*)d_in[13];
    const float* bp   = (const float*)d_in[14];
    const float* W1   = (const float*)d_in[15];
    const float* b1   = (const float*)d_in[16];
    const float* W2   = (const float*)d_in[17];
    const float* b2   = (const float*)d_in[18];
    float* out = (float*)d_out;

    float *p_xn, *p_tok, *p_q, *p_k, *p_v, *p_attn, *p_x1, *p_h2, *p_act;
    cudaGetSymbolAddress((void**)&p_xn,   g_xn);
    cudaGetSymbolAddress((void**)&p_tok,  g_tokens);
    cudaGetSymbolAddress((void**)&p_q,    g_q);
    cudaGetSymbolAddress((void**)&p_k,    g_k);
    cudaGetSymbolAddress((void**)&p_v,    g_v);
    cudaGetSymbolAddress((void**)&p_attn, g_attn);
    cudaGetSymbolAddress((void**)&p_x1,   g_x1);
    cudaGetSymbolAddress((void**)&p_h2,   g_h2);
    cudaGetSymbolAddress((void**)&p_act,  g_act);

    const size_t gemm_smem = (size_t)2 * STG_ * sizeof(float);                 // 70656
    const size_t attn_smem = (size_t)ATTN_SMEM_FLOATS * sizeof(float);         // ~105KB
    cudaFuncSetAttribute(gemm_tf32_kernel, cudaFuncAttributeMaxDynamicSharedMemorySize, (int)gemm_smem);
    cudaFuncSetAttribute(attn_kernel, cudaFuncAttributeMaxDynamicSharedMemorySize, (int)attn_smem);

    // 0. mask bit-pack
    mask_pack_kernel<<<(BB * NN * NW + 7) / 8, 256>>>(mask);

    // 1. LN1 + concat tokens
    ln1_concat_kernel<<<BB * TT, 256>>>(x, ce, ln1g, ln1b);

    // 2. Q/K/V projections
    dim3 gq((BB * NN + GBM - 1) / GBM, CC / GBN);   // (128, 6)
    dim3 gkv((BB * TT + GBM - 1) / GBM, CC / GBN);  // (168, 6)
    gemm_tf32_kernel<<<gq, 256, gemm_smem>>>(p_xn,  Wq, bq, nullptr, p_q, BB * NN, CC, CC, EPI_BIAS);
    gemm_tf32_kernel<<<gkv, 256, gemm_smem>>>(p_tok, Wk, bk, nullptr, p_k, BB * TT, CC, CC, EPI_BIAS);
    gemm_tf32_kernel<<<gkv, 256, gemm_smem>>>(p_tok, Wv, bv, nullptr, p_v, BB * TT, CC, CC, EPI_BIAS);

    // 3. Attention (flash)
    attn_kernel<<<dim3(NN / AQ, HH, BB), 256, attn_smem>>>();

    // 4. Output projection + residual
    gemm_tf32_kernel<<<gq, 256, gemm_smem>>>(p_attn, Wp, bp, p_xn, p_x1, BB * NN, CC, CC, EPI_ADD);

    // 5. LN2
    ln2_kernel<<<BB * NN, 256>>>(ln2g, ln2b);

    // 6. MLP
    dim3 g1((BB * NN + GBM - 1) / GBM, MLPD / GBN); // (128, 24)
    gemm_tf32_kernel<<<g1, 256, gemm_smem>>>(p_h2, W1, b1, nullptr, p_act, BB * NN, MLPD, CC, EPI_GELU);
    gemm_tf32_kernel<<<gq, 256, gemm_smem>>>(p_act, W2, b2, p_x1, out, BB * NN, CC, MLPD, EPI_ADD);
}

// round 6
// speedup vs baseline: 5.6677x; 1.9614x over previous
#include <cuda_runtime.h>
#include <cuda_fp16.h>
#include <mma.h>
#include <math.h>

using namespace nvcuda;

// Problem dims
#define BB 16
#define NN 1024
#define LL 313
#define CC 768
#define HH 12
#define DHD 64
#define TT (NN + LL)       // 1337
#define TPAD 1344          // 21 * 64
#define MLPD 3072
#define NW 42              // TPAD/32 mask words per row
#define QKVD 2304
#define MTOK (BB * TT)     // 21392 token rows

// ---------------- scratch (device globals) -----------------------------------
__device__ float  g_xn[(size_t)BB * NN * CC];
__device__ __half g_tokens_h[(size_t)MTOK * CC];
__device__ float  g_qkv[(size_t)MTOK * QKVD];
__device__ __half g_attn_h[(size_t)BB * NN * CC];
__device__ float  g_x1[(size_t)BB * NN * CC];
__device__ __half g_h2_h[(size_t)BB * NN * CC];
__device__ __half g_act_h[(size_t)BB * NN * MLPD];
__device__ unsigned g_mbits[(size_t)BB * NN * NW];
__device__ __half g_wqkv_h[(size_t)CC * QKVD];
__device__ __half g_wp_h[(size_t)CC * CC];
__device__ __half g_w1_h[(size_t)CC * MLPD];
__device__ __half g_w2_h[(size_t)MLPD * CC];
__device__ float  g_bqkv[QKVD];

// ---------------- helpers -----------------------------------------------------
__device__ __forceinline__ void cp16(unsigned dst, const void* src) {
    asm volatile("cp.async.cg.shared.global [%0], [%1], 16;\n" :: "r"(dst), "l"(src));
}

// ---------------- weight convert/pack: fp32 [K,N] -> half [K,stride] ----------
__global__ void wpack_kernel(const float* __restrict__ W, __half* __restrict__ dst,
                             int K, int N, int stride, int off)
{
    int i = blockIdx.x * 256 + threadIdx.x;
    if (i >= K * N) return;
    int k = i / N, n = i - k * N;
    dst[(size_t)k * stride + off + n] = __float2half(W[i]);
}

__global__ void biaspack_kernel(const float* __restrict__ bq,
                                const float* __restrict__ bk,
                                const float* __restrict__ bv)
{
    int i = blockIdx.x * 256 + threadIdx.x;
    if (i < CC) g_bqkv[i] = bq[i];
    else if (i < 2 * CC) g_bqkv[i] = bk[i - CC];
    else if (i < QKVD) g_bqkv[i] = bv[i - 2 * CC];
}

// ---------------- mask bit-packing --------------------------------------------
__global__ void mask_pack_kernel(const int* __restrict__ mask)
{
    int widx = blockIdx.x * 8 + (threadIdx.x >> 5);
    int lane = threadIdx.x & 31;
    if (widx >= BB * NN * NW) return;
    int w = widx % NW;
    int row = widx / NW;
    int gc = w * 32 + lane;
    int mval = (gc < TT) ? mask[(size_t)row * TT + gc] : 0;
    unsigned bits = __ballot_sync(~0u, mval != 0);
    if (lane == 0) g_mbits[widx] = bits;
}

// ---------------- LayerNorm 1 + concat ----------------------------------------
__global__ void ln1_concat_kernel(const float* __restrict__ x,
                                  const float* __restrict__ ce,
                                  const float* __restrict__ gam,
                                  const float* __restrict__ bet)
{
    int row = blockIdx.x;
    int b = row / TT;
    int t = row - b * TT;
    int tid = threadIdx.x;

    if (t >= NN) {
        const float* src = ce + ((size_t)b * LL + (t - NN)) * CC;
        __half* dst = g_tokens_h + (size_t)row * CC;
        for (int i = tid; i < CC; i += 256) dst[i] = __float2half(src[i]);
        return;
    }

    const float* src = x + ((size_t)b * NN + t) * CC;
    float v0 = src[tid], v1 = src[tid + 256], v2 = src[tid + 512];
    float s = v0 + v1 + v2;
    float s2 = v0 * v0 + v1 * v1 + v2 * v2;

    __shared__ float rs[8], rs2[8];
    int lane = tid & 31, warp = tid >> 5;
    #pragma unroll
    for (int o = 16; o; o >>= 1) {
        s  += __shfl_xor_sync(~0u, s, o);
        s2 += __shfl_xor_sync(~0u, s2, o);
    }
    if (lane == 0) { rs[warp] = s; rs2[warp] = s2; }
    __syncthreads();
    if (tid == 0) {
        float a = 0.f, c = 0.f;
        #pragma unroll
        for (int i = 0; i < 8; i++) { a += rs[i]; c += rs2[i]; }
        rs[0] = a; rs2[0] = c;
    }
    __syncthreads();
    float mu = rs[0] * (1.0f / CC);
    float var = rs2[0] * (1.0f / CC) - mu * mu;
    float rstd = rsqrtf(var + 1e-5f);

    float* oxn = g_xn + ((size_t)b * NN + t) * CC;
    __half* otk = g_tokens_h + (size_t)row * CC;
    int i = tid;
    float o = (v0 - mu) * rstd * gam[i] + bet[i]; oxn[i] = o; otk[i] = __float2half(o);
    i = tid + 256;
    o = (v1 - mu) * rstd * gam[i] + bet[i]; oxn[i] = o; otk[i] = __float2half(o);
    i = tid + 512;
    o = (v2 - mu) * rstd * gam[i] + bet[i]; oxn[i] = o; otk[i] = __float2half(o);
}

// ---------------- LayerNorm 2 (x1 -> h2 half) ---------------------------------
__global__ void ln2_kernel(const float* __restrict__ gam,
                           const float* __restrict__ bet)
{
    int row = blockIdx.x;
    int tid = threadIdx.x;
    const float* src = g_x1 + (size_t)row * CC;
    float v0 = src[tid], v1 = src[tid + 256], v2 = src[tid + 512];
    float s = v0 + v1 + v2;
    float s2 = v0 * v0 + v1 * v1 + v2 * v2;

    __shared__ float rs[8], rs2[8];
    int lane = tid & 31, warp = tid >> 5;
    #pragma unroll
    for (int o = 16; o; o >>= 1) {
        s  += __shfl_xor_sync(~0u, s, o);
        s2 += __shfl_xor_sync(~0u, s2, o);
    }
    if (lane == 0) { rs[warp] = s; rs2[warp] = s2; }
    __syncthreads();
    if (tid == 0) {
        float a = 0.f, c = 0.f;
        #pragma unroll
        for (int i = 0; i < 8; i++) { a += rs[i]; c += rs2[i]; }
        rs[0] = a; rs2[0] = c;
    }
    __syncthreads();
    float mu = rs[0] * (1.0f / CC);
    float var = rs2[0] * (1.0f / CC) - mu * mu;
    float rstd = rsqrtf(var + 1e-5f);

    __half* dst = g_h2_h + (size_t)row * CC;
    int i = tid;
    dst[i] = __float2half((v0 - mu) * rstd * gam[i] + bet[i]);
    i = tid + 256;
    dst[i] = __float2half((v1 - mu) * rstd * gam[i] + bet[i]);
    i = tid + 512;
    dst[i] = __float2half((v2 - mu) * rstd * gam[i] + bet[i]);
}

// ---------------- fp16 WMMA GEMM, 3-stage cp.async ----------------------------
// out[M,N] = epi(A[M,K](half) @ W[K,N](half) + bias[N])
#define GBM 128
#define GBN 128
#define GBK 32
#define LDA_H 56            // halves; 112B row stride (16B mult, conflict-free LDSM)
#define LDB_H 136           // halves; 272B row stride
#define ASTG (GBM * LDA_H)  // 7168 halves
#define BSTG (GBK * LDB_H)  // 4352 halves
#define STGB ((ASTG + BSTG) * 2)   // 23040 bytes per stage
#define NSTG 3
#define GEMM_SMEM (NSTG * STGB)    // 69120 >= 128*132*4 epilogue stage
#define LDS_ 132
#define EPI_BIAS 0
#define EPI_GELU 1
#define EPI_ADD  2

__global__ void __launch_bounds__(256, 2)
gemm_h_kernel(const __half* __restrict__ A, const __half* __restrict__ W,
              const float* __restrict__ bias, const float* __restrict__ res,
              void* __restrict__ out, int M, int N, int K, int epi, int outHalf)
{
    extern __shared__ __align__(16) char smraw[];
    unsigned sbase = (unsigned)__cvta_generic_to_shared(smraw);

    int m0 = blockIdx.x * GBM;
    int n0 = blockIdx.y * GBN;
    int tid = threadIdx.x;
    int warp = tid >> 5;
    int wm = warp >> 2;   // 0..1
    int wn = warp & 3;    // 0..3

    wmma::fragment<wmma::accumulator, 16, 16, 16, float> acc[4][2];
    #pragma unroll
    for (int i = 0; i < 4; i++)
        #pragma unroll
        for (int j = 0; j < 2; j++)
            wmma::fill_fragment(acc[i][j], 0.0f);

    auto load_stage = [&](int c, int buf) {
        unsigned sa = sbase + buf * STGB;
        unsigned sb = sa + ASTG * 2;
        int k0 = c * GBK;
        // A: 128 rows x 32 halves (64B) = 512 x 16B chunks
        #pragma unroll
        for (int p = 0; p < 2; p++) {
            int idx = tid + p * 256;
            int r = idx >> 2, cc = idx & 3;
            int gr = m0 + r; if (gr >= M) gr = M - 1;
            cp16(sa + (r * LDA_H + cc * 8) * 2, A + (size_t)gr * K + k0 + cc * 8);
        }
        // B: 32 rows x 128 halves (256B) = 512 x 16B chunks
        #pragma unroll
        for (int p = 0; p < 2; p++) {
            int idx = tid + p * 256;
            int r = idx >> 4, cc = idx & 15;
            cp16(sb + (r * LDB_H + cc * 8) * 2, W + (size_t)(k0 + r) * N + n0 + cc * 8);
        }
        asm volatile("cp.async.commit_group;\n");
    };

    int KT = K / GBK;
    load_stage(0, 0);
    load_stage(1, 1);
    load_stage(2, 2);

    for (int kt = 0; kt < KT; kt++) {
        asm volatile("cp.async.wait_group 2;\n");
        __syncthreads();

        const __half* sA = (const __half*)(smraw + (kt % 3) * STGB);
        const __half* sB = sA + ASTG;
        #pragma unroll
        for (int kk = 0; kk < GBK; kk += 16) {
            wmma::fragment<wmma::matrix_a, 16, 16, 16, __half, wmma::row_major> af[4];
            wmma::fragment<wmma::matrix_b, 16, 16, 16, __half, wmma::row_major> bf[2];
            #pragma unroll
            for (int i = 0; i < 4; i++)
                wmma::load_matrix_sync(af[i], sA + (wm * 64 + i * 16) * LDA_H + kk, LDA_H);
            #pragma unroll
            for (int j = 0; j < 2; j++)
                wmma::load_matrix_sync(bf[j], sB + kk * LDB_H + wn * 32 + j * 16, LDB_H);
            #pragma unroll
            for (int i = 0; i < 4; i++)
                #pragma unroll
                for (int j = 0; j < 2; j++)
                    wmma::mma_sync(acc[i][j], af[i], bf[j], acc[i][j]);
        }
        __syncthreads();

        if (kt + 3 < KT) load_stage(kt + 3, (kt + 3) % 3);
        else asm volatile("cp.async.commit_group;\n");
    }

    // epilogue via fp32 smem stage
    float* stage = (float*)smraw;
    #pragma unroll
    for (int i = 0; i < 4; i++)
        #pragma unroll
        for (int j = 0; j < 2; j++)
            wmma::store_matrix_sync(stage + (wm * 64 + i * 16) * LDS_ + wn * 32 + j * 16,
                                    acc[i][j], LDS_, wmma::mem_row_major);
    __syncthreads();

    for (int e = tid; e < 128 * 32; e += 256) {
        int r = e >> 5, c4 = e & 31;
        int gr = m0 + r, gc = n0 + c4 * 4;
        if (gr < M) {
            float4 v = *(float4*)(stage + r * LDS_ + c4 * 4);
            float4 bb = *(const float4*)(bias + gc);
            v.x += bb.x; v.y += bb.y; v.z += bb.z; v.w += bb.w;
            if (epi == EPI_GELU) {
                v.x = 0.5f * v.x * (1.0f + erff(v.x * 0.70710678118654752f));
                v.y = 0.5f * v.y * (1.0f + erff(v.y * 0.70710678118654752f));
                v.z = 0.5f * v.z * (1.0f + erff(v.z * 0.70710678118654752f));
                v.w = 0.5f * v.w * (1.0f + erff(v.w * 0.70710678118654752f));
            } else if (epi == EPI_ADD) {
                float4 rr = *(const float4*)(res + (size_t)gr * N + gc);
                v.x += rr.x; v.y += rr.y; v.z += rr.z; v.w += rr.w;
            }
            if (outHalf) {
                __half2* oh = (__half2*)((__half*)out + (size_t)gr * N + gc);
                oh[0] = __floats2half2_rn(v.x, v.y);
                oh[1] = __floats2half2_rn(v.z, v.w);
            } else {
                *(float4*)((float*)out + (size_t)gr * N + gc) = v;
            }
        }
    }
}

// ---------------- Flash-style attention (tf32 WMMA) ---------------------------
#define AQ 64
#define LDH 68
#define A_Q   0
#define A_K   (64 * LDH)
#define A_V   (2 * 64 * LDH)
#define A_P   (3 * 64 * LDH)
#define A_O   (4 * 64 * LDH)
#define A_ST  (5 * 64 * LDH)
#define A_M   (6 * 64 * LDH)
#define A_L   (A_M + 64)
#define A_SF  (A_L + 64)
#define ATTN_SMEM_FLOATS (A_SF + 64)

__global__ void __launch_bounds__(256, 2)
attn_kernel()
{
    extern __shared__ float sm[];
    int q0 = blockIdx.x * AQ;
    int h = blockIdx.y;
    int b = blockIdx.z;
    int tid = threadIdx.x;
    int warp = tid >> 5, lane = tid & 31;
    int wr = warp >> 1;
    int wc = warp & 1;

    if (tid < 64) { sm[A_M + tid] = -1e30f; sm[A_L + tid] = 0.f; }
    #pragma unroll
    for (int j = 0; j < 4; j++) {
        int e = tid + j * 256;
        int r = e >> 4, c4 = e & 15;
        *(float4*)(sm + A_O + r * LDH + c4 * 4) = make_float4(0.f, 0.f, 0.f, 0.f);
    }

    {
        const float* qb = g_qkv + ((size_t)b * TT + q0) * QKVD + h * DHD;
        #pragma unroll
        for (int j = 0; j < 4; j++) {
            int e = tid + j * 256;
            int r = e >> 4, c4 = e & 15;
            float4 v = *(const float4*)(qb + (size_t)r * QKVD + c4 * 4);
            v.x *= 0.125f; v.y *= 0.125f; v.z *= 0.125f; v.w *= 0.125f;
            *(float4*)(sm + A_Q + r * LDH + c4 * 4) = v;
        }
    }

    const float* kb = g_qkv + (size_t)b * TT * QKVD + CC + h * DHD;
    const float* vb = g_qkv + (size_t)b * TT * QKVD + 2 * CC + h * DHD;
    const unsigned* mb = g_mbits + ((size_t)b * NN + q0) * NW;

    for (int t0 = 0; t0 < TPAD; t0 += 64) {
        #pragma unroll
        for (int j = 0; j < 8; j++) {
            int e = tid + j * 256;
            int half_ = e >> 10;
            int ee = e & 1023;
            int r = ee >> 4, c4 = ee & 15;
            int row = t0 + r;
            float4 v = make_float4(0.f, 0.f, 0.f, 0.f);
            if (row < TT) {
                const float* src = (half_ ? vb : kb) + (size_t)row * QKVD + c4 * 4;
                v = *(const float4*)src;
            }
            *(float4*)(sm + (half_ ? A_V : A_K) + r * LDH + c4 * 4) = v;
        }
        __syncthreads();

        {
            wmma::fragment<wmma::accumulator, 16, 16, 8, float> sacc[2];
            wmma::fill_fragment(sacc[0], 0.0f);
            wmma::fill_fragment(sacc[1], 0.0f);
            #pragma unroll
            for (int kk = 0; kk < DHD; kk += 8) {
                wmma::fragment<wmma::matrix_a, 16, 16, 8, wmma::precision::tf32, wmma::row_major> af;
                wmma::fragment<wmma::matrix_b, 16, 16, 8, wmma::precision::tf32, wmma::col_major> bf;
                wmma::load_matrix_sync(af, sm + A_Q + (wr * 16) * LDH + kk, LDH);
                #pragma unroll
                for (int j = 0; j < 2; j++) {
                    wmma::load_matrix_sync(bf, sm + A_K + (wc * 32 + j * 16) * LDH + kk, LDH);
                    wmma::mma_sync(sacc[j], af, bf, sacc[j]);
                }
            }
            #pragma unroll
            for (int j = 0; j < 2; j++)
                wmma::store_matrix_sync(sm + A_P + (wr * 16) * LDH + wc * 32 + j * 16,
                                        sacc[j], LDH, wmma::mem_row_major);
        }
        __syncthreads();

        #pragma unroll
        for (int i = 0; i < 8; i++) {
            int r = warp * 8 + i;
            float* prow = sm + A_P + r * LDH;
            unsigned w0 = mb[(size_t)r * NW + (t0 >> 5)];
            unsigned w1 = mb[(size_t)r * NW + (t0 >> 5) + 1];
            bool v0 = (w0 >> lane) & 1u;
            bool v1 = (w1 >> lane) & 1u;
            float x0 = v0 ? prow[lane] : -1e30f;
            float x1 = v1 ? prow[lane + 32] : -1e30f;
            float cm = fmaxf(x0, x1);
            #pragma unroll
            for (int o = 16; o; o >>= 1) cm = fmaxf(cm, __shfl_xor_sync(~0u, cm, o));
            float m_old = sm[A_M + r];
            float m_new = fmaxf(m_old, cm);
            float p0 = v0 ? __expf(x0 - m_new) : 0.f;
            float p1 = v1 ? __expf(x1 - m_new) : 0.f;
            float ps = p0 + p1;
            #pragma unroll
            for (int o = 16; o; o >>= 1) ps += __shfl_xor_sync(~0u, ps, o);
            prow[lane] = p0;
            prow[lane + 32] = p1;
            if (lane == 0) {
                float sf = __expf(m_old - m_new);
                sm[A_SF + r] = sf;
                sm[A_L + r] = sm[A_L + r] * sf + ps;
                sm[A_M + r] = m_new;
            }
        }
        __syncthreads();

        {
            wmma::fragment<wmma::accumulator, 16, 16, 8, float> oacc[2];
            wmma::fill_fragment(oacc[0], 0.0f);
            wmma::fill_fragment(oacc[1], 0.0f);
            #pragma unroll
            for (int kk = 0; kk < 64; kk += 8) {
                wmma::fragment<wmma::matrix_a, 16, 16, 8, wmma::precision::tf32, wmma::row_major> af;
                wmma::fragment<wmma::matrix_b, 16, 16, 8, wmma::precision::tf32, wmma::row_major> bf;
                wmma::load_matrix_sync(af, sm + A_P + (wr * 16) * LDH + kk, LDH);
                #pragma unroll
                for (int j = 0; j < 2; j++) {
                    wmma::load_matrix_sync(bf, sm + A_V + kk * LDH + wc * 32 + j * 16, LDH);
                    wmma::mma_sync(oacc[j], af, bf, oacc[j]);
                }
            }
            #pragma unroll
            for (int j = 0; j < 2; j++)
                wmma::store_matrix_sync(sm + A_ST + (wr * 16) * LDH + wc * 32 + j * 16,
                                        oacc[j], LDH, wmma::mem_row_major);
        }
        __syncthreads();

        #pragma unroll
        for (int j = 0; j < 4; j++) {
            int e = tid + j * 256;
            int r = e >> 4, c4 = e & 15;
            float sf = sm[A_SF + r];
            float4 o = *(float4*)(sm + A_O + r * LDH + c4 * 4);
            float4 st = *(float4*)(sm + A_ST + r * LDH + c4 * 4);
            o.x = o.x * sf + st.x; o.y = o.y * sf + st.y;
            o.z = o.z * sf + st.z; o.w = o.w * sf + st.w;
            *(float4*)(sm + A_O + r * LDH + c4 * 4) = o;
        }
        __syncthreads();
    }

    __half* ob = g_attn_h + ((size_t)b * NN + q0) * CC + h * DHD;
    #pragma unroll
    for (int j = 0; j < 4; j++) {
        int e = tid + j * 256;
        int r = e >> 4, c4 = e & 15;
        float inv = 1.0f / sm[A_L + r];
        float4 o = *(float4*)(sm + A_O + r * LDH + c4 * 4);
        __half2* dst = (__half2*)(ob + (size_t)r * CC + c4 * 4);
        dst[0] = __floats2half2_rn(o.x * inv, o.y * inv);
        dst[1] = __floats2half2_rn(o.z * inv, o.w * inv);
    }
}

// ---------------- launch -----------------------------------------------------
extern "C" void kernel_launch(void* const* d_in, const int* in_sizes, int n_in,
                              void* d_out, int out_size)
{
    const float* x    = (const float*)d_in[0];
    const float* ce   = (const float*)d_in[1];
    const int*   mask = (const int*)  d_in[2];
    const float* ln1g = (const float*)d_in[3];
    const float* ln1b = (const float*)d_in[4];
    const float* ln2g = (const float*)d_in[5];
    const float* ln2b = (const float*)d_in[6];
    const float* Wq   = (const float*)d_in[7];
    const float* bq   = (const float*)d_in[8];
    const float* Wk   = (const float*)d_in[9];
    const float* bk   = (const float*)d_in[10];
    const float* Wv   = (const float*)d_in[11];
    const float* bv   = (const float*)d_in[12];
    const float* Wp   = (const float*)d_in[13];
    const float* bp   = (const float*)d_in[14];
    const float* W1   = (const float*)d_in[15];
    const float* b1   = (const float*)d_in[16];
    const float* W2   = (const float*)d_in[17];
    const float* b2   = (const float*)d_in[18];
    float* out = (float*)d_out;

    float *p_xn, *p_qkv, *p_x1, *p_bqkv;
    __half *p_tok, *p_attn, *p_h2, *p_act, *p_wqkv, *p_wp, *p_w1, *p_w2;
    cudaGetSymbolAddress((void**)&p_xn,   g_xn);
    cudaGetSymbolAddress((void**)&p_tok,  g_tokens_h);
    cudaGetSymbolAddress((void**)&p_qkv,  g_qkv);
    cudaGetSymbolAddress((void**)&p_attn, g_attn_h);
    cudaGetSymbolAddress((void**)&p_x1,   g_x1);
    cudaGetSymbolAddress((void**)&p_h2,   g_h2_h);
    cudaGetSymbolAddress((void**)&p_act,  g_act_h);
    cudaGetSymbolAddress((void**)&p_wqkv, g_wqkv_h);
    cudaGetSymbolAddress((void**)&p_wp,   g_wp_h);
    cudaGetSymbolAddress((void**)&p_w1,   g_w1_h);
    cudaGetSymbolAddress((void**)&p_w2,   g_w2_h);
    cudaGetSymbolAddress((void**)&p_bqkv, g_bqkv);

    const size_t attn_smem = (size_t)ATTN_SMEM_FLOATS * sizeof(float);
    cudaFuncSetAttribute(gemm_h_kernel, cudaFuncAttributeMaxDynamicSharedMemorySize, GEMM_SMEM);
    cudaFuncSetAttribute(attn_kernel, cudaFuncAttributeMaxDynamicSharedMemorySize, (int)attn_smem);

    // weight packs (fp32 -> half)
    int nCC = CC * CC, nCM = CC * MLPD;
    wpack_kernel<<<(nCC + 255) / 256, 256>>>(Wq, p_wqkv, CC, CC, QKVD, 0);
    wpack_kernel<<<(nCC + 255) / 256, 256>>>(Wk, p_wqkv, CC, CC, QKVD, CC);
    wpack_kernel<<<(nCC + 255) / 256, 256>>>(Wv, p_wqkv, CC, CC, QKVD, 2 * CC);
    wpack_kernel<<<(nCC + 255) / 256, 256>>>(Wp, p_wp, CC, CC, CC, 0);
    wpack_kernel<<<(nCM + 255) / 256, 256>>>(W1, p_w1, CC, MLPD, MLPD, 0);
    wpack_kernel<<<(nCM + 255) / 256, 256>>>(W2, p_w2, MLPD, CC, CC, 0);
    biaspack_kernel<<<(QKVD + 255) / 256, 256>>>(bq, bk, bv);

    mask_pack_kernel<<<(BB * NN * NW + 7) / 8, 256>>>(mask);
    ln1_concat_kernel<<<BB * TT, 256>>>(x, ce, ln1g, ln1b);

    // fused QKV: tokens_h [21392,768] @ Wqkv_h [768,2304] -> g_qkv fp32
    gemm_h_kernel<<<dim3((MTOK + 127) / 128, QKVD / 128), 256, GEMM_SMEM>>>(
        p_tok, p_wqkv, p_bqkv, nullptr, p_qkv, MTOK, QKVD, CC, EPI_BIAS, 0);

    // attention (flash, tf32) -> g_attn_h half
    attn_kernel<<<dim3(NN / AQ, HH, BB), 256, attn_smem>>>();

    // proj + residual: x1 = xn + attn @ Wp + bp  (fp32 out)
    gemm_h_kernel<<<dim3(BB * NN / 128, CC / 128), 256, GEMM_SMEM>>>(
        p_attn, p_wp, bp, p_xn, p_x1, BB * NN, CC, CC, EPI_ADD, 0);

    ln2_kernel<<<BB * NN, 256>>>(ln2g, ln2b);

    // MLP1: h2_h @ W1_h + b1, GELU -> act_h (half out)
    gemm_h_kernel<<<dim3(BB * NN / 128, MLPD / 128), 256, GEMM_SMEM>>>(
        p_h2, p_w1, b1, nullptr, p_act, BB * NN, MLPD, CC, EPI_GELU, 1);

    // MLP2: act_h @ W2_h + b2 + x1 -> out (fp32)
    gemm_h_kernel<<<dim3(BB * NN / 128, CC / 128), 256, GEMM_SMEM>>>(
        p_act, p_w2, b2, p_x1, out, BB * NN, CC, MLPD, EPI_ADD, 0);
}

// round 8
// speedup vs baseline: 7.9004x; 1.3939x over previous
#include <cuda_runtime.h>
#include <cuda_fp16.h>
#include <mma.h>
#include <math.h>

using namespace nvcuda;

// Problem dims
#define BB 16
#define NN 1024
#define LL 313
#define CC 768
#define HH 12
#define DHD 64
#define TT (NN + LL)       // 1337
#define TPAD 1344          // 21 * 64
#define MLPD 3072
#define NW 42              // TPAD/32 mask words per row
#define QKVD 2304
#define MTOK (BB * TT)     // 21392 token rows

// ---------------- scratch (device globals) -----------------------------------
__device__ float  g_xn[(size_t)BB * NN * CC];
__device__ __half g_tokens_h[(size_t)MTOK * CC];
__device__ __half g_qkv_h[(size_t)MTOK * QKVD];
__device__ __half g_attn_h[(size_t)BB * NN * CC];
__device__ float  g_x1[(size_t)BB * NN * CC];
__device__ __half g_h2_h[(size_t)BB * NN * CC];
__device__ __half g_act_h[(size_t)BB * NN * MLPD];
__device__ unsigned g_mbits[(size_t)BB * NN * NW];
__device__ __half g_wqkv_h[(size_t)CC * QKVD];
__device__ __half g_wp_h[(size_t)CC * CC];
__device__ __half g_w1_h[(size_t)CC * MLPD];
__device__ __half g_w2_h[(size_t)MLPD * CC];
__device__ float  g_bqkv[QKVD];

// ---------------- helpers -----------------------------------------------------
__device__ __forceinline__ void cp16(unsigned dst, const void* src) {
    asm volatile("cp.async.cg.shared.global [%0], [%1], 16;\n" :: "r"(dst), "l"(src));
}

// ---------------- weight convert/pack -----------------------------------------
__global__ void wpack_kernel(const float* __restrict__ W, __half* __restrict__ dst,
                             int K, int N, int stride, int off)
{
    int i = blockIdx.x * 256 + threadIdx.x;
    if (i >= K * N) return;
    int k = i / N, n = i - k * N;
    dst[(size_t)k * stride + off + n] = __float2half(W[i]);
}

__global__ void biaspack_kernel(const float* __restrict__ bq,
                                const float* __restrict__ bk,
                                const float* __restrict__ bv)
{
    int i = blockIdx.x * 256 + threadIdx.x;
    if (i < CC) g_bqkv[i] = bq[i];
    else if (i < 2 * CC) g_bqkv[i] = bk[i - CC];
    else if (i < QKVD) g_bqkv[i] = bv[i - 2 * CC];
}

// ---------------- mask bit-packing --------------------------------------------
__global__ void mask_pack_kernel(const int* __restrict__ mask)
{
    int widx = blockIdx.x * 8 + (threadIdx.x >> 5);
    int lane = threadIdx.x & 31;
    if (widx >= BB * NN * NW) return;
    int w = widx % NW;
    int row = widx / NW;
    int gc = w * 32 + lane;
    int mval = (gc < TT) ? mask[(size_t)row * TT + gc] : 0;
    unsigned bits = __ballot_sync(~0u, mval != 0);
    if (lane == 0) g_mbits[widx] = bits;
}

// ---------------- LayerNorm 1 + concat ----------------------------------------
__global__ void ln1_concat_kernel(const float* __restrict__ x,
                                  const float* __restrict__ ce,
                                  const float* __restrict__ gam,
                                  const float* __restrict__ bet)
{
    int row = blockIdx.x;
    int b = row / TT;
    int t = row - b * TT;
    int tid = threadIdx.x;

    if (t >= NN) {
        const float* src = ce + ((size_t)b * LL + (t - NN)) * CC;
        __half* dst = g_tokens_h + (size_t)row * CC;
        for (int i = tid; i < CC; i += 256) dst[i] = __float2half(src[i]);
        return;
    }

    const float* src = x + ((size_t)b * NN + t) * CC;
    float v0 = src[tid], v1 = src[tid + 256], v2 = src[tid + 512];
    float s = v0 + v1 + v2;
    float s2 = v0 * v0 + v1 * v1 + v2 * v2;

    __shared__ float rs[8], rs2[8];
    int lane = tid & 31, warp = tid >> 5;
    #pragma unroll
    for (int o = 16; o; o >>= 1) {
        s  += __shfl_xor_sync(~0u, s, o);
        s2 += __shfl_xor_sync(~0u, s2, o);
    }
    if (lane == 0) { rs[warp] = s; rs2[warp] = s2; }
    __syncthreads();
    if (tid == 0) {
        float a = 0.f, c = 0.f;
        #pragma unroll
        for (int i = 0; i < 8; i++) { a += rs[i]; c += rs2[i]; }
        rs[0] = a; rs2[0] = c;
    }
    __syncthreads();
    float mu = rs[0] * (1.0f / CC);
    float var = rs2[0] * (1.0f / CC) - mu * mu;
    float rstd = rsqrtf(var + 1e-5f);

    float* oxn = g_xn + ((size_t)b * NN + t) * CC;
    __half* otk = g_tokens_h + (size_t)row * CC;
    int i = tid;
    float o = (v0 - mu) * rstd * gam[i] + bet[i]; oxn[i] = o; otk[i] = __float2half(o);
    i = tid + 256;
    o = (v1 - mu) * rstd * gam[i] + bet[i]; oxn[i] = o; otk[i] = __float2half(o);
    i = tid + 512;
    o = (v2 - mu) * rstd * gam[i] + bet[i]; oxn[i] = o; otk[i] = __float2half(o);
}

// ---------------- LayerNorm 2 (x1 -> h2 half) ---------------------------------
__global__ void ln2_kernel(const float* __restrict__ gam,
                           const float* __restrict__ bet)
{
    int row = blockIdx.x;
    int tid = threadIdx.x;
    const float* src = g_x1 + (size_t)row * CC;
    float v0 = src[tid], v1 = src[tid + 256], v2 = src[tid + 512];
    float s = v0 + v1 + v2;
    float s2 = v0 * v0 + v1 * v1 + v2 * v2;

    __shared__ float rs[8], rs2[8];
    int lane = tid & 31, warp = tid >> 5;
    #pragma unroll
    for (int o = 16; o; o >>= 1) {
        s  += __shfl_xor_sync(~0u, s, o);
        s2 += __shfl_xor_sync(~0u, s2, o);
    }
    if (lane == 0) { rs[warp] = s; rs2[warp] = s2; }
    __syncthreads();
    if (tid == 0) {
        float a = 0.f, c = 0.f;
        #pragma unroll
        for (int i = 0; i < 8; i++) { a += rs[i]; c += rs2[i]; }
        rs[0] = a; rs2[0] = c;
    }
    __syncthreads();
    float mu = rs[0] * (1.0f / CC);
    float var = rs2[0] * (1.0f / CC) - mu * mu;
    float rstd = rsqrtf(var + 1e-5f);

    __half* dst = g_h2_h + (size_t)row * CC;
    int i = tid;
    dst[i] = __float2half((v0 - mu) * rstd * gam[i] + bet[i]);
    i = tid + 256;
    dst[i] = __float2half((v1 - mu) * rstd * gam[i] + bet[i]);
    i = tid + 512;
    dst[i] = __float2half((v2 - mu) * rstd * gam[i] + bet[i]);
}

// ---------------- fp16 WMMA GEMM, 3-stage cp.async ----------------------------
#define GBM 128
#define GBN 128
#define GBK 32
#define LDA_H 56
#define LDB_H 136
#define ASTG (GBM * LDA_H)
#define BSTG (GBK * LDB_H)
#define STGB ((ASTG + BSTG) * 2)
#define NSTG 3
#define GEMM_SMEM (NSTG * STGB)
#define LDS_ 132
#define EPI_BIAS 0
#define EPI_GELU 1
#define EPI_ADD  2

__global__ void __launch_bounds__(256, 2)
gemm_h_kernel(const __half* __restrict__ A, const __half* __restrict__ W,
              const float* __restrict__ bias, const float* __restrict__ res,
              void* __restrict__ out, int M, int N, int K, int epi, int outHalf)
{
    extern __shared__ __align__(16) char smraw[];
    unsigned sbase = (unsigned)__cvta_generic_to_shared(smraw);

    int m0 = blockIdx.x * GBM;
    int n0 = blockIdx.y * GBN;
    int tid = threadIdx.x;
    int warp = tid >> 5;
    int wm = warp >> 2;
    int wn = warp & 3;

    wmma::fragment<wmma::accumulator, 16, 16, 16, float> acc[4][2];
    #pragma unroll
    for (int i = 0; i < 4; i++)
        #pragma unroll
        for (int j = 0; j < 2; j++)
            wmma::fill_fragment(acc[i][j], 0.0f);

    auto load_stage = [&](int c, int buf) {
        unsigned sa = sbase + buf * STGB;
        unsigned sb = sa + ASTG * 2;
        int k0 = c * GBK;
        #pragma unroll
        for (int p = 0; p < 2; p++) {
            int idx = tid + p * 256;
            int r = idx >> 2, cc = idx & 3;
            int gr = m0 + r; if (gr >= M) gr = M - 1;
            cp16(sa + (r * LDA_H + cc * 8) * 2, A + (size_t)gr * K + k0 + cc * 8);
        }
        #pragma unroll
        for (int p = 0; p < 2; p++) {
            int idx = tid + p * 256;
            int r = idx >> 4, cc = idx & 15;
            cp16(sb + (r * LDB_H + cc * 8) * 2, W + (size_t)(k0 + r) * N + n0 + cc * 8);
        }
        asm volatile("cp.async.commit_group;\n");
    };

    int KT = K / GBK;
    load_stage(0, 0);
    load_stage(1, 1);
    load_stage(2, 2);

    for (int kt = 0; kt < KT; kt++) {
        asm volatile("cp.async.wait_group 2;\n");
        __syncthreads();

        const __half* sA = (const __half*)(smraw + (kt % 3) * STGB);
        const __half* sB = sA + ASTG;
        #pragma unroll
        for (int kk = 0; kk < GBK; kk += 16) {
            wmma::fragment<wmma::matrix_a, 16, 16, 16, __half, wmma::row_major> af[4];
            wmma::fragment<wmma::matrix_b, 16, 16, 16, __half, wmma::row_major> bf[2];
            #pragma unroll
            for (int i = 0; i < 4; i++)
                wmma::load_matrix_sync(af[i], sA + (wm * 64 + i * 16) * LDA_H + kk, LDA_H);
            #pragma unroll
            for (int j = 0; j < 2; j++)
                wmma::load_matrix_sync(bf[j], sB + kk * LDB_H + wn * 32 + j * 16, LDB_H);
            #pragma unroll
            for (int i = 0; i < 4; i++)
                #pragma unroll
                for (int j = 0; j < 2; j++)
                    wmma::mma_sync(acc[i][j], af[i], bf[j], acc[i][j]);
        }
        __syncthreads();

        if (kt + 3 < KT) load_stage(kt + 3, (kt + 3) % 3);
        else asm volatile("cp.async.commit_group;\n");
    }

    float* stage = (float*)smraw;
    #pragma unroll
    for (int i = 0; i < 4; i++)
        #pragma unroll
        for (int j = 0; j < 2; j++)
            wmma::store_matrix_sync(stage + (wm * 64 + i * 16) * LDS_ + wn * 32 + j * 16,
                                    acc[i][j], LDS_, wmma::mem_row_major);
    __syncthreads();

    for (int e = tid; e < 128 * 32; e += 256) {
        int r = e >> 5, c4 = e & 31;
        int gr = m0 + r, gc = n0 + c4 * 4;
        if (gr < M) {
            float4 v = *(float4*)(stage + r * LDS_ + c4 * 4);
            float4 bb = *(const float4*)(bias + gc);
            v.x += bb.x; v.y += bb.y; v.z += bb.z; v.w += bb.w;
            if (epi == EPI_GELU) {
                v.x = 0.5f * v.x * (1.0f + erff(v.x * 0.70710678118654752f));
                v.y = 0.5f * v.y * (1.0f + erff(v.y * 0.70710678118654752f));
                v.z = 0.5f * v.z * (1.0f + erff(v.z * 0.70710678118654752f));
                v.w = 0.5f * v.w * (1.0f + erff(v.w * 0.70710678118654752f));
            } else if (epi == EPI_ADD) {
                float4 rr = *(const float4*)(res + (size_t)gr * N + gc);
                v.x += rr.x; v.y += rr.y; v.z += rr.z; v.w += rr.w;
            }
            if (outHalf) {
                __half2* oh = (__half2*)((__half*)out + (size_t)gr * N + gc);
                oh[0] = __floats2half2_rn(v.x, v.y);
                oh[1] = __floats2half2_rn(v.z, v.w);
            } else {
                *(float4*)((float*)out + (size_t)gr * N + gc) = v;
            }
        }
    }
}

// ---------------- Flash-style attention (fp16 WMMA) ---------------------------
// smem layout (bytes): Q,K,V,P half tiles 64 x 72 (9216 ea); S/stage fp32 64x68;
// O fp32 64x68; m/l/sf 64 fp32 each.
#define AQ 64
#define LQH 72                     // half stride
#define LOF 68                     // float stride
#define OFF_Q  0
#define OFF_K  9216
#define OFF_V  18432
#define OFF_P  27648
#define OFF_S  36864               // fp32 scores / PV stage (reused)
#define OFF_O  54272
#define OFF_M  71680
#define OFF_L  71936
#define OFF_SF 72192
#define ATTN_SMEM (72448)

__global__ void __launch_bounds__(256, 2)
attn_kernel()
{
    extern __shared__ __align__(16) char smc[];
    __half* sQ = (__half*)(smc + OFF_Q);
    __half* sK = (__half*)(smc + OFF_K);
    __half* sV = (__half*)(smc + OFF_V);
    __half* sP = (__half*)(smc + OFF_P);
    float*  sS = (float*)(smc + OFF_S);
    float*  sO = (float*)(smc + OFF_O);
    float*  sM = (float*)(smc + OFF_M);
    float*  sL = (float*)(smc + OFF_L);
    float*  sSF = (float*)(smc + OFF_SF);

    int q0 = blockIdx.x * AQ;
    int h = blockIdx.y;
    int b = blockIdx.z;
    int tid = threadIdx.x;
    int warp = tid >> 5, lane = tid & 31;
    int wr = warp >> 1;   // 0..3 : 16-row group
    int wc = warp & 1;    // 0..1 : 32-col group

    if (tid < 64) { sM[tid] = -1e30f; sL[tid] = 0.f; }
    #pragma unroll
    for (int j = 0; j < 4; j++) {
        int e = tid + j * 256;
        int r = e >> 4, c4 = e & 15;
        *(float4*)(sO + r * LOF + c4 * 4) = make_float4(0.f, 0.f, 0.f, 0.f);
    }

    // load Q tile (half, unscaled; scale applied in softmax)
    {
        const __half* qb = g_qkv_h + ((size_t)b * TT + q0) * QKVD + h * DHD;
        #pragma unroll
        for (int j = 0; j < 2; j++) {
            int e = tid + j * 256;           // 512 chunks: 64 rows x 8 x (8 halves)
            int r = e >> 3, c8 = e & 7;
            float4 v = *(const float4*)(qb + (size_t)r * QKVD + c8 * 8);
            *(float4*)(sQ + r * LQH + c8 * 8) = v;
        }
    }

    const __half* kb = g_qkv_h + (size_t)b * TT * QKVD + CC + h * DHD;
    const __half* vb = g_qkv_h + (size_t)b * TT * QKVD + 2 * CC + h * DHD;
    const unsigned* mb = g_mbits + ((size_t)b * NN + q0) * NW;
    const float4 zero4 = make_float4(0.f, 0.f, 0.f, 0.f);

    for (int t0 = 0; t0 < TPAD; t0 += 64) {
        // load K and V chunks (half), zero-pad past TT
        #pragma unroll
        for (int j = 0; j < 4; j++) {
            int e = tid + j * 256;              // 0..1023
            int half_ = e >> 9;                 // 0=K, 1=V
            int ee = e & 511;
            int r = ee >> 3, c8 = ee & 7;
            int row = t0 + r;
            float4 v = zero4;
            if (row < TT) {
                const __half* src = (half_ ? vb : kb) + (size_t)row * QKVD + c8 * 8;
                v = *(const float4*)src;
            }
            *(float4*)((half_ ? sV : sK) + r * LQH + c8 * 8) = v;
        }
        __syncthreads();

        // S = Q @ K^T (fp16 HMMA, fp32 acc)
        {
            wmma::fragment<wmma::accumulator, 16, 16, 16, float> sacc[2];
            wmma::fill_fragment(sacc[0], 0.0f);
            wmma::fill_fragment(sacc[1], 0.0f);
            #pragma unroll
            for (int kk = 0; kk < DHD; kk += 16) {
                wmma::fragment<wmma::matrix_a, 16, 16, 16, __half, wmma::row_major> af;
                wmma::fragment<wmma::matrix_b, 16, 16, 16, __half, wmma::col_major> bf;
                wmma::load_matrix_sync(af, sQ + (wr * 16) * LQH + kk, LQH);
                #pragma unroll
                for (int j = 0; j < 2; j++) {
                    wmma::load_matrix_sync(bf, sK + (wc * 32 + j * 16) * LQH + kk, LQH);
                    wmma::mma_sync(sacc[j], af, bf, sacc[j]);
                }
            }
            #pragma unroll
            for (int j = 0; j < 2; j++)
                wmma::store_matrix_sync(sS + (wr * 16) * LOF + wc * 32 + j * 16,
                                        sacc[j], LOF, wmma::mem_row_major);
        }
        __syncthreads();

        // online softmax (scale 0.125 here); write P as half
        #pragma unroll
        for (int i = 0; i < 8; i++) {
            int r = warp * 8 + i;
            float* srow = sS + r * LOF;
            unsigned w0 = mb[(size_t)r * NW + (t0 >> 5)];
            unsigned w1 = mb[(size_t)r * NW + (t0 >> 5) + 1];
            bool v0 = (w0 >> lane) & 1u;
            bool v1 = (w1 >> lane) & 1u;
            float x0 = v0 ? srow[lane] * 0.125f : -1e30f;
            float x1 = v1 ? srow[lane + 32] * 0.125f : -1e30f;
            float cm = fmaxf(x0, x1);
            #pragma unroll
            for (int o = 16; o; o >>= 1) cm = fmaxf(cm, __shfl_xor_sync(~0u, cm, o));
            float m_old = sM[r];
            float m_new = fmaxf(m_old, cm);
            float p0 = v0 ? __expf(x0 - m_new) : 0.f;
            float p1 = v1 ? __expf(x1 - m_new) : 0.f;
            float ps = p0 + p1;
            #pragma unroll
            for (int o = 16; o; o >>= 1) ps += __shfl_xor_sync(~0u, ps, o);
            __half2* prow = (__half2*)(sP + r * LQH);
            ((__half*)prow)[lane] = __float2half_rn(p0);
            ((__half*)prow)[lane + 32] = __float2half_rn(p1);
            if (lane == 0) {
                float sf = __expf(m_old - m_new);
                sSF[r] = sf;
                sL[r] = sL[r] * sf + ps;
                sM[r] = m_new;
            }
        }
        __syncthreads();

        // PV = P @ V (fp16 HMMA) -> stage (reuse sS)
        {
            wmma::fragment<wmma::accumulator, 16, 16, 16, float> oacc[2];
            wmma::fill_fragment(oacc[0], 0.0f);
            wmma::fill_fragment(oacc[1], 0.0f);
            #pragma unroll
            for (int kk = 0; kk < 64; kk += 16) {
                wmma::fragment<wmma::matrix_a, 16, 16, 16, __half, wmma::row_major> af;
                wmma::fragment<wmma::matrix_b, 16, 16, 16, __half, wmma::row_major> bf;
                wmma::load_matrix_sync(af, sP + (wr * 16) * LQH + kk, LQH);
                #pragma unroll
                for (int j = 0; j < 2; j++) {
                    wmma::load_matrix_sync(bf, sV + kk * LQH + wc * 32 + j * 16, LQH);
                    wmma::mma_sync(oacc[j], af, bf, oacc[j]);
                }
            }
            #pragma unroll
            for (int j = 0; j < 2; j++)
                wmma::store_matrix_sync(sS + (wr * 16) * LOF + wc * 32 + j * 16,
                                        oacc[j], LOF, wmma::mem_row_major);
        }
        __syncthreads();

        // O = O * sf + stage
        #pragma unroll
        for (int j = 0; j < 4; j++) {
            int e = tid + j * 256;
            int r = e >> 4, c4 = e & 15;
            float sf = sSF[r];
            float4 o = *(float4*)(sO + r * LOF + c4 * 4);
            float4 st = *(float4*)(sS + r * LOF + c4 * 4);
            o.x = o.x * sf + st.x; o.y = o.y * sf + st.y;
            o.z = o.z * sf + st.z; o.w = o.w * sf + st.w;
            *(float4*)(sO + r * LOF + c4 * 4) = o;
        }
        __syncthreads();
    }

    __half* ob = g_attn_h + ((size_t)b * NN + q0) * CC + h * DHD;
    #pragma unroll
    for (int j = 0; j < 4; j++) {
        int e = tid + j * 256;
        int r = e >> 4, c4 = e & 15;
        float inv = 1.0f / sL[r];
        float4 o = *(float4*)(sO + r * LOF + c4 * 4);
        __half2* dst = (__half2*)(ob + (size_t)r * CC + c4 * 4);
        dst[0] = __floats2half2_rn(o.x * inv, o.y * inv);
        dst[1] = __floats2half2_rn(o.z * inv, o.w * inv);
    }
}

// ---------------- launch -----------------------------------------------------
extern "C" void kernel_launch(void* const* d_in, const int* in_sizes, int n_in,
                              void* d_out, int out_size)
{
    const float* x    = (const float*)d_in[0];
    const float* ce   = (const float*)d_in[1];
    const int*   mask = (const int*)  d_in[2];
    const float* ln1g = (const float*)d_in[3];
    const float* ln1b = (const float*)d_in[4];
    const float* ln2g = (const float*)d_in[5];
    const float* ln2b = (const float*)d_in[6];
    const float* Wq   = (const float*)d_in[7];
    const float* bq   = (const float*)d_in[8];
    const float* Wk   = (const float*)d_in[9];
    const float* bk   = (const float*)d_in[10];
    const float* Wv   = (const float*)d_in[11];
    const float* bv   = (const float*)d_in[12];
    const float* Wp   = (const float*)d_in[13];
    const float* bp   = (const float*)d_in[14];
    const float* W1   = (const float*)d_in[15];
    const float* b1   = (const float*)d_in[16];
    const float* W2   = (const float*)d_in[17];
    const float* b2   = (const float*)d_in[18];
    float* out = (float*)d_out;

    float *p_xn, *p_x1, *p_bqkv;
    __half *p_tok, *p_qkv, *p_attn, *p_h2, *p_act, *p_wqkv, *p_wp, *p_w1, *p_w2;
    cudaGetSymbolAddress((void**)&p_xn,   g_xn);
    cudaGetSymbolAddress((void**)&p_tok,  g_tokens_h);
    cudaGetSymbolAddress((void**)&p_qkv,  g_qkv_h);
    cudaGetSymbolAddress((void**)&p_attn, g_attn_h);
    cudaGetSymbolAddress((void**)&p_x1,   g_x1);
    cudaGetSymbolAddress((void**)&p_h2,   g_h2_h);
    cudaGetSymbolAddress((void**)&p_act,  g_act_h);
    cudaGetSymbolAddress((void**)&p_wqkv, g_wqkv_h);
    cudaGetSymbolAddress((void**)&p_wp,   g_wp_h);
    cudaGetSymbolAddress((void**)&p_w1,   g_w1_h);
    cudaGetSymbolAddress((void**)&p_w2,   g_w2_h);
    cudaGetSymbolAddress((void**)&p_bqkv, g_bqkv);

    cudaFuncSetAttribute(gemm_h_kernel, cudaFuncAttributeMaxDynamicSharedMemorySize, GEMM_SMEM);
    cudaFuncSetAttribute(attn_kernel, cudaFuncAttributeMaxDynamicSharedMemorySize, ATTN_SMEM);

    int nCC = CC * CC, nCM = CC * MLPD;
    wpack_kernel<<<(nCC + 255) / 256, 256>>>(Wq, p_wqkv, CC, CC, QKVD, 0);
    wpack_kernel<<<(nCC + 255) / 256, 256>>>(Wk, p_wqkv, CC, CC, QKVD, CC);
    wpack_kernel<<<(nCC + 255) / 256, 256>>>(Wv, p_wqkv, CC, CC, QKVD, 2 * CC);
    wpack_kernel<<<(nCC + 255) / 256, 256>>>(Wp, p_wp, CC, CC, CC, 0);
    wpack_kernel<<<(nCM + 255) / 256, 256>>>(W1, p_w1, CC, MLPD, MLPD, 0);
    wpack_kernel<<<(nCM + 255) / 256, 256>>>(W2, p_w2, MLPD, CC, CC, 0);
    biaspack_kernel<<<(QKVD + 255) / 256, 256>>>(bq, bk, bv);

    mask_pack_kernel<<<(BB * NN * NW + 7) / 8, 256>>>(mask);
    ln1_concat_kernel<<<BB * TT, 256>>>(x, ce, ln1g, ln1b);

    // fused QKV -> half
    gemm_h_kernel<<<dim3((MTOK + 127) / 128, QKVD / 128), 256, GEMM_SMEM>>>(
        p_tok, p_wqkv, p_bqkv, nullptr, p_qkv, MTOK, QKVD, CC, EPI_BIAS, 1);

    // attention (flash, fp16)
    attn_kernel<<<dim3(NN / AQ, HH, BB), 256, ATTN_SMEM>>>();

    // proj + residual: x1 = xn + attn @ Wp + bp (fp32 out)
    gemm_h_kernel<<<dim3(BB * NN / 128, CC / 128), 256, GEMM_SMEM>>>(
        p_attn, p_wp, bp, p_xn, p_x1, BB * NN, CC, CC, EPI_ADD, 0);

    ln2_kernel<<<BB * NN, 256>>>(ln2g, ln2b);

    // MLP
    gemm_h_kernel<<<dim3(BB * NN / 128, MLPD / 128), 256, GEMM_SMEM>>>(
        p_h2, p_w1, b1, nullptr, p_act, BB * NN, MLPD, CC, EPI_GELU, 1);
    gemm_h_kernel<<<dim3(BB * NN / 128, CC / 128), 256, GEMM_SMEM>>>(
        p_act, p_w2, b2, p_x1, out, BB * NN, CC, MLPD, EPI_ADD, 0);
}

// round 10
// speedup vs baseline: 8.5893x; 1.0872x over previous
#include <cuda_runtime.h>
#include <cuda_fp16.h>
#include <mma.h>
#include <math.h>

using namespace nvcuda;

// Problem dims
#define BB 16
#define NN 1024
#define LL 313
#define CC 768
#define HH 12
#define DHD 64
#define TT (NN + LL)       // 1337
#define TPAD 1344          // 21 * 64
#define MLPD 3072
#define NW 42              // TPAD/32 mask words per row
#define QKVD 2304
#define MTOK (BB * TT)     // 21392 token rows

// ---------------- scratch (device globals) -----------------------------------
__device__ float  g_xn[(size_t)BB * NN * CC];
__device__ __half g_tokens_h[(size_t)MTOK * CC];
__device__ __half g_qkv_h[(size_t)MTOK * QKVD];
__device__ __half g_attn_h[(size_t)BB * NN * CC];
__device__ float  g_x1[(size_t)BB * NN * CC];
__device__ __half g_h2_h[(size_t)BB * NN * CC];
__device__ __half g_act_h[(size_t)BB * NN * MLPD];
__device__ unsigned g_mbits[(size_t)BB * NN * NW];
__device__ __half g_wqkv_h[(size_t)CC * QKVD];
__device__ __half g_wp_h[(size_t)CC * CC];
__device__ __half g_w1_h[(size_t)CC * MLPD];
__device__ __half g_w2_h[(size_t)MLPD * CC];
__device__ float  g_bqkv[QKVD];

// ---------------- helpers -----------------------------------------------------
__device__ __forceinline__ void cp16(unsigned dst, const void* src) {
    asm volatile("cp.async.cg.shared.global [%0], [%1], 16;\n" :: "r"(dst), "l"(src));
}
__device__ __forceinline__ void cp16_pred(unsigned dst, const void* src, bool p) {
    int bytes = p ? 16 : 0;
    asm volatile("cp.async.cg.shared.global [%0], [%1], 16, %2;\n"
                 :: "r"(dst), "l"(src), "r"(bytes));
}
__device__ __forceinline__ int remap_row(int r, int doRemap) {
    return doRemap ? ((r >> 10) * TT + (r & 1023)) : r;   // NN == 1024
}

// ---------------- weight convert/pack -----------------------------------------
__global__ void wpack_kernel(const float* __restrict__ W, __half* __restrict__ dst,
                             int K, int N, int stride, int off)
{
    int i = blockIdx.x * 256 + threadIdx.x;
    if (i >= K * N) return;
    int k = i / N, n = i - k * N;
    dst[(size_t)k * stride + off + n] = __float2half(W[i]);
}

__global__ void biaspack_kernel(const float* __restrict__ bq,
                                const float* __restrict__ bk,
                                const float* __restrict__ bv)
{
    int i = blockIdx.x * 256 + threadIdx.x;
    if (i < CC) g_bqkv[i] = bq[i];
    else if (i < 2 * CC) g_bqkv[i] = bk[i - CC];
    else if (i < QKVD) g_bqkv[i] = bv[i - 2 * CC];
}

// ---------------- mask bit-packing --------------------------------------------
__global__ void mask_pack_kernel(const int* __restrict__ mask)
{
    int widx = blockIdx.x * 8 + (threadIdx.x >> 5);
    int lane = threadIdx.x & 31;
    if (widx >= BB * NN * NW) return;
    int w = widx % NW;
    int row = widx / NW;
    int gc = w * 32 + lane;
    int mval = (gc < TT) ? mask[(size_t)row * TT + gc] : 0;
    unsigned bits = __ballot_sync(~0u, mval != 0);
    if (lane == 0) g_mbits[widx] = bits;
}

// ---------------- LayerNorm 1 + concat ----------------------------------------
__global__ void ln1_concat_kernel(const float* __restrict__ x,
                                  const float* __restrict__ ce,
                                  const float* __restrict__ gam,
                                  const float* __restrict__ bet)
{
    int row = blockIdx.x;
    int b = row / TT;
    int t = row - b * TT;
    int tid = threadIdx.x;

    if (t >= NN) {
        const float* src = ce + ((size_t)b * LL + (t - NN)) * CC;
        __half* dst = g_tokens_h + (size_t)row * CC;
        for (int i = tid; i < CC; i += 256) dst[i] = __float2half(src[i]);
        return;
    }

    const float* src = x + ((size_t)b * NN + t) * CC;
    float v0 = src[tid], v1 = src[tid + 256], v2 = src[tid + 512];
    float s = v0 + v1 + v2;
    float s2 = v0 * v0 + v1 * v1 + v2 * v2;

    __shared__ float rs[8], rs2[8];
    int lane = tid & 31, warp = tid >> 5;
    #pragma unroll
    for (int o = 16; o; o >>= 1) {
        s  += __shfl_xor_sync(~0u, s, o);
        s2 += __shfl_xor_sync(~0u, s2, o);
    }
    if (lane == 0) { rs[warp] = s; rs2[warp] = s2; }
    __syncthreads();
    if (tid == 0) {
        float a = 0.f, c = 0.f;
        #pragma unroll
        for (int i = 0; i < 8; i++) { a += rs[i]; c += rs2[i]; }
        rs[0] = a; rs2[0] = c;
    }
    __syncthreads();
    float mu = rs[0] * (1.0f / CC);
    float var = rs2[0] * (1.0f / CC) - mu * mu;
    float rstd = rsqrtf(var + 1e-5f);

    float* oxn = g_xn + ((size_t)b * NN + t) * CC;
    __half* otk = g_tokens_h + (size_t)row * CC;
    int i = tid;
    float o = (v0 - mu) * rstd * gam[i] + bet[i]; oxn[i] = o; otk[i] = __float2half(o);
    i = tid + 256;
    o = (v1 - mu) * rstd * gam[i] + bet[i]; oxn[i] = o; otk[i] = __float2half(o);
    i = tid + 512;
    o = (v2 - mu) * rstd * gam[i] + bet[i]; oxn[i] = o; otk[i] = __float2half(o);
}

// ---------------- LayerNorm 2 (x1 -> h2 half) ---------------------------------
__global__ void ln2_kernel(const float* __restrict__ gam,
                           const float* __restrict__ bet)
{
    int row = blockIdx.x;
    int tid = threadIdx.x;
    const float* src = g_x1 + (size_t)row * CC;
    float v0 = src[tid], v1 = src[tid + 256], v2 = src[tid + 512];
    float s = v0 + v1 + v2;
    float s2 = v0 * v0 + v1 * v1 + v2 * v2;

    __shared__ float rs[8], rs2[8];
    int lane = tid & 31, warp = tid >> 5;
    #pragma unroll
    for (int o = 16; o; o >>= 1) {
        s  += __shfl_xor_sync(~0u, s, o);
        s2 += __shfl_xor_sync(~0u, s2, o);
    }
    if (lane == 0) { rs[warp] = s; rs2[warp] = s2; }
    __syncthreads();
    if (tid == 0) {
        float a = 0.f, c = 0.f;
        #pragma unroll
        for (int i = 0; i < 8; i++) { a += rs[i]; c += rs2[i]; }
        rs[0] = a; rs2[0] = c;
    }
    __syncthreads();
    float mu = rs[0] * (1.0f / CC);
    float var = rs2[0] * (1.0f / CC) - mu * mu;
    float rstd = rsqrtf(var + 1e-5f);

    __half* dst = g_h2_h + (size_t)row * CC;
    int i = tid;
    dst[i] = __float2half((v0 - mu) * rstd * gam[i] + bet[i]);
    i = tid + 256;
    dst[i] = __float2half((v1 - mu) * rstd * gam[i] + bet[i]);
    i = tid + 512;
    dst[i] = __float2half((v2 - mu) * rstd * gam[i] + bet[i]);
}

// ---------------- fp16 WMMA GEMM, 4-stage cp.async ----------------------------
#define GBM 128
#define GBN 128
#define GBK 32
#define LDA_H 56
#define LDB_H 136
#define ASTG (GBM * LDA_H)
#define BSTG (GBK * LDB_H)
#define STGB ((ASTG + BSTG) * 2)   // 23040 B
#define NSTG 4
#define GEMM_SMEM (NSTG * STGB)    // 92160 B
#define LDS_ 132
#define EPI_BIAS 0
#define EPI_GELU 1
#define EPI_ADD  2

__global__ void __launch_bounds__(256, 2)
gemm_h_kernel(const __half* __restrict__ A, const __half* __restrict__ W,
              const float* __restrict__ bias, const float* __restrict__ res,
              void* __restrict__ out, int M, int N, int K, int epi, int outHalf,
              int ldA, int ldW, int ldout, int rowRemap)
{
    extern __shared__ __align__(16) char smraw[];
    unsigned sbase = (unsigned)__cvta_generic_to_shared(smraw);

    int m0 = blockIdx.x * GBM;
    int n0 = blockIdx.y * GBN;
    int tid = threadIdx.x;
    int warp = tid >> 5;
    int wm = warp >> 2;
    int wn = warp & 3;

    wmma::fragment<wmma::accumulator, 16, 16, 16, float> acc[4][2];
    #pragma unroll
    for (int i = 0; i < 4; i++)
        #pragma unroll
        for (int j = 0; j < 2; j++)
            wmma::fill_fragment(acc[i][j], 0.0f);

    auto load_stage = [&](int c, int buf) {
        unsigned sa = sbase + buf * STGB;
        unsigned sb = sa + ASTG * 2;
        int k0 = c * GBK;
        #pragma unroll
        for (int p = 0; p < 2; p++) {
            int idx = tid + p * 256;
            int r = idx >> 2, cc = idx & 3;
            int gr = m0 + r; if (gr >= M) gr = M - 1;
            gr = remap_row(gr, rowRemap);
            cp16(sa + (r * LDA_H + cc * 8) * 2, A + (size_t)gr * ldA + k0 + cc * 8);
        }
        #pragma unroll
        for (int p = 0; p < 2; p++) {
            int idx = tid + p * 256;
            int r = idx >> 4, cc = idx & 15;
            cp16(sb + (r * LDB_H + cc * 8) * 2, W + (size_t)(k0 + r) * ldW + n0 + cc * 8);
        }
        asm volatile("cp.async.commit_group;\n");
    };

    int KT = K / GBK;
    load_stage(0, 0);
    load_stage(1, 1);
    load_stage(2, 2);
    load_stage(3, 3);

    for (int kt = 0; kt < KT; kt++) {
        asm volatile("cp.async.wait_group 3;\n");
        __syncthreads();

        const __half* sA = (const __half*)(smraw + (kt & 3) * STGB);
        const __half* sB = sA + ASTG;
        #pragma unroll
        for (int kk = 0; kk < GBK; kk += 16) {
            wmma::fragment<wmma::matrix_a, 16, 16, 16, __half, wmma::row_major> af[4];
            wmma::fragment<wmma::matrix_b, 16, 16, 16, __half, wmma::row_major> bf[2];
            #pragma unroll
            for (int i = 0; i < 4; i++)
                wmma::load_matrix_sync(af[i], sA + (wm * 64 + i * 16) * LDA_H + kk, LDA_H);
            #pragma unroll
            for (int j = 0; j < 2; j++)
                wmma::load_matrix_sync(bf[j], sB + kk * LDB_H + wn * 32 + j * 16, LDB_H);
            #pragma unroll
            for (int i = 0; i < 4; i++)
                #pragma unroll
                for (int j = 0; j < 2; j++)
                    wmma::mma_sync(acc[i][j], af[i], bf[j], acc[i][j]);
        }
        __syncthreads();

        if (kt + 4 < KT) load_stage(kt + 4, (kt + 4) & 3);
        else asm volatile("cp.async.commit_group;\n");
    }

    float* stage = (float*)smraw;
    #pragma unroll
    for (int i = 0; i < 4; i++)
        #pragma unroll
        for (int j = 0; j < 2; j++)
            wmma::store_matrix_sync(stage + (wm * 64 + i * 16) * LDS_ + wn * 32 + j * 16,
                                    acc[i][j], LDS_, wmma::mem_row_major);
    __syncthreads();

    for (int e = tid; e < 128 * 32; e += 256) {
        int r = e >> 5, c4 = e & 31;
        int gr = m0 + r, gc = n0 + c4 * 4;
        if (gr < M) {
            int go = remap_row(gr, rowRemap);
            float4 v = *(float4*)(stage + r * LDS_ + c4 * 4);
            float4 bb = *(const float4*)(bias + gc);
            v.x += bb.x; v.y += bb.y; v.z += bb.z; v.w += bb.w;
            if (epi == EPI_GELU) {
                v.x = 0.5f * v.x * (1.0f + erff(v.x * 0.70710678118654752f));
                v.y = 0.5f * v.y * (1.0f + erff(v.y * 0.70710678118654752f));
                v.z = 0.5f * v.z * (1.0f + erff(v.z * 0.70710678118654752f));
                v.w = 0.5f * v.w * (1.0f + erff(v.w * 0.70710678118654752f));
            } else if (epi == EPI_ADD) {
                float4 rr = *(const float4*)(res + (size_t)gr * ldout + gc);
                v.x += rr.x; v.y += rr.y; v.z += rr.z; v.w += rr.w;
            }
            if (outHalf) {
                __half2* oh = (__half2*)((__half*)out + (size_t)go * ldout + gc);
                oh[0] = __floats2half2_rn(v.x, v.y);
                oh[1] = __floats2half2_rn(v.z, v.w);
            } else {
                *(float4*)((float*)out + (size_t)go * ldout + gc) = v;
            }
        }
    }
}

// ---------------- Flash attention v2 (fp16 WMMA, O in registers) ---------------
#define AQ 64
#define LQH 72                     // half stride (Q,K,V,P)
#define LOF 68                     // float stride (S)
#define OFF_Q  0
#define OFF_K0 9216
#define OFF_V0 18432
#define OFF_K1 27648
#define OFF_V1 36864
#define OFF_P  46080
#define OFF_S  55296
#define OFF_M  72704
#define OFF_L  72960
#define OFF_SF 73216
#define ATTN_SMEM 73472

__global__ void __launch_bounds__(256, 2)
attn_kernel()
{
    extern __shared__ __align__(16) char smc[];
    unsigned sbase = (unsigned)__cvta_generic_to_shared(smc);
    __half* sQ = (__half*)(smc + OFF_Q);
    __half* sP = (__half*)(smc + OFF_P);
    float*  sS = (float*)(smc + OFF_S);
    float*  sM = (float*)(smc + OFF_M);
    float*  sL = (float*)(smc + OFF_L);
    float*  sSF = (float*)(smc + OFF_SF);

    int q0 = blockIdx.x * AQ;
    int h = blockIdx.y;
    int b = blockIdx.z;
    int tid = threadIdx.x;
    int warp = tid >> 5, lane = tid & 31;
    int wr = warp >> 1;   // 0..3 : 16-row group
    int wc = warp & 1;    // 0..1 : 32-col group

    if (tid < 64) { sM[tid] = -1e30f; sL[tid] = 0.f; }

    const __half* kb = g_qkv_h + (size_t)b * TT * QKVD + CC + h * DHD;
    const __half* vb = g_qkv_h + (size_t)b * TT * QKVD + 2 * CC + h * DHD;
    const unsigned* mb = g_mbits + ((size_t)b * NN + q0) * NW;

    // cp.async loader for one 64-row K+V chunk into buffer bi (zero-fill past TT)
    auto load_kv = [&](int t0, int bi) {
        unsigned kB = sbase + (bi ? OFF_K1 : OFF_K0);
        unsigned vB = sbase + (bi ? OFF_V1 : OFF_V0);
        #pragma unroll
        for (int j = 0; j < 4; j++) {
            int e = tid + j * 256;              // 0..1023
            int isv = e >> 9;                   // 0=K, 1=V
            int ee = e & 511;
            int r = ee >> 3, c8 = ee & 7;
            int row = t0 + r;
            bool p = row < TT;
            int rs = p ? row : (TT - 1);
            const __half* src = (isv ? vb : kb) + (size_t)rs * QKVD + c8 * 8;
            cp16_pred((isv ? vB : kB) + (r * LQH + c8 * 8) * 2, src, p);
        }
        asm volatile("cp.async.commit_group;\n");
    };

    // prologue: chunk 0 load + Q load
    load_kv(0, 0);
    {
        const __half* qb = g_qkv_h + ((size_t)b * TT + q0) * QKVD + h * DHD;
        #pragma unroll
        for (int j = 0; j < 2; j++) {
            int e = tid + j * 256;           // 512 chunks: 64 rows x 8 x (8 halves)
            int r = e >> 3, c8 = e & 7;
            float4 v = *(const float4*)(qb + (size_t)r * QKVD + c8 * 8);
            *(float4*)(sQ + r * LQH + c8 * 8) = v;
        }
    }
    asm volatile("cp.async.wait_group 0;\n");
    __syncthreads();

    wmma::fragment<wmma::accumulator, 16, 16, 16, float> oacc[2];
    wmma::fill_fragment(oacc[0], 0.0f);
    wmma::fill_fragment(oacc[1], 0.0f);

    const int NCH = TPAD / 64;   // 21
    for (int c = 0; c < NCH; c++) {
        int cur = c & 1;
        if (c + 1 < NCH) load_kv((c + 1) * 64, cur ^ 1);
        else asm volatile("cp.async.commit_group;\n");

        const __half* sK = (const __half*)(smc + (cur ? OFF_K1 : OFF_K0));
        const __half* sV = (const __half*)(smc + (cur ? OFF_V1 : OFF_V0));

        // S = Q @ K^T
        {
            wmma::fragment<wmma::accumulator, 16, 16, 16, float> sacc[2];
            wmma::fill_fragment(sacc[0], 0.0f);
            wmma::fill_fragment(sacc[1], 0.0f);
            #pragma unroll
            for (int kk = 0; kk < DHD; kk += 16) {
                wmma::fragment<wmma::matrix_a, 16, 16, 16, __half, wmma::row_major> af;
                wmma::fragment<wmma::matrix_b, 16, 16, 16, __half, wmma::col_major> bf;
                wmma::load_matrix_sync(af, sQ + (wr * 16) * LQH + kk, LQH);
                #pragma unroll
                for (int j = 0; j < 2; j++) {
                    wmma::load_matrix_sync(bf, sK + (wc * 32 + j * 16) * LQH + kk, LQH);
                    wmma::mma_sync(sacc[j], af, bf, sacc[j]);
                }
            }
            #pragma unroll
            for (int j = 0; j < 2; j++)
                wmma::store_matrix_sync(sS + (wr * 16) * LOF + wc * 32 + j * 16,
                                        sacc[j], LOF, wmma::mem_row_major);
        }
        __syncthreads();

        // online softmax (scale 0.125); P as half, sf per row
        #pragma unroll
        for (int i = 0; i < 8; i++) {
            int r = warp * 8 + i;
            float* srow = sS + r * LOF;
            unsigned w0 = mb[(size_t)r * NW + c * 2];
            unsigned w1 = mb[(size_t)r * NW + c * 2 + 1];
            bool v0 = (w0 >> lane) & 1u;
            bool v1 = (w1 >> lane) & 1u;
            float x0 = v0 ? srow[lane] * 0.125f : -1e30f;
            float x1 = v1 ? srow[lane + 32] * 0.125f : -1e30f;
            float cm = fmaxf(x0, x1);
            #pragma unroll
            for (int o = 16; o; o >>= 1) cm = fmaxf(cm, __shfl_xor_sync(~0u, cm, o));
            float m_old = sM[r];
            float m_new = fmaxf(m_old, cm);
            float p0 = v0 ? __expf(x0 - m_new) : 0.f;
            float p1 = v1 ? __expf(x1 - m_new) : 0.f;
            float ps = p0 + p1;
            #pragma unroll
            for (int o = 16; o; o >>= 1) ps += __shfl_xor_sync(~0u, ps, o);
            __half* prow = sP + r * LQH;
            prow[lane] = __float2half_rn(p0);
            prow[lane + 32] = __float2half_rn(p1);
            if (lane == 0) {
                float sf = __expf(m_old - m_new);
                sSF[r] = sf;
                sL[r] = sL[r] * sf + ps;
                sM[r] = m_new;
            }
        }
        __syncthreads();

        // rescale O fragments, then O += P @ V
        {
            float sf0 = sSF[wr * 16 + (lane >> 2)];
            float sf1 = sSF[wr * 16 + (lane >> 2) + 8];
            #pragma unroll
            for (int j = 0; j < 2; j++) {
                oacc[j].x[0] *= sf0; oacc[j].x[1] *= sf0;
                oacc[j].x[2] *= sf1; oacc[j].x[3] *= sf1;
                oacc[j].x[4] *= sf0; oacc[j].x[5] *= sf0;
                oacc[j].x[6] *= sf1; oacc[j].x[7] *= sf1;
            }
            #pragma unroll
            for (int kk = 0; kk < 64; kk += 16) {
                wmma::fragment<wmma::matrix_a, 16, 16, 16, __half, wmma::row_major> af;
                wmma::fragment<wmma::matrix_b, 16, 16, 16, __half, wmma::row_major> bf;
                wmma::load_matrix_sync(af, sP + (wr * 16) * LQH + kk, LQH);
                #pragma unroll
                for (int j = 0; j < 2; j++) {
                    wmma::load_matrix_sync(bf, sV + kk * LQH + wc * 32 + j * 16, LQH);
                    wmma::mma_sync(oacc[j], af, bf, oacc[j]);
                }
            }
        }

        asm volatile("cp.async.wait_group 0;\n");
        __syncthreads();
    }

    // finalize: scale by 1/l in-register, stage via sS, coalesced half writes
    {
        float inv0 = 1.0f / sL[wr * 16 + (lane >> 2)];
        float inv1 = 1.0f / sL[wr * 16 + (lane >> 2) + 8];
        #pragma unroll
        for (int j = 0; j < 2; j++) {
            oacc[j].x[0] *= inv0; oacc[j].x[1] *= inv0;
            oacc[j].x[2] *= inv1; oacc[j].x[3] *= inv1;
            oacc[j].x[4] *= inv0; oacc[j].x[5] *= inv0;
            oacc[j].x[6] *= inv1; oacc[j].x[7] *= inv1;
        }
        #pragma unroll
        for (int j = 0; j < 2; j++)
            wmma::store_matrix_sync(sS + (wr * 16) * LOF + wc * 32 + j * 16,
                                    oacc[j], LOF, wmma::mem_row_major);
    }
    __syncthreads();

    __half* ob = g_attn_h + ((size_t)b * NN + q0) * CC + h * DHD;
    #pragma unroll
    for (int j = 0; j < 2; j++) {
        int e = tid + j * 256;           // 512 chunks: 64 rows x 8 x (8 halves)
        int r = e >> 3, c8 = e & 7;
        const float* srow = sS + r * LOF + c8 * 8;
        __half2 h2[4];
        h2[0] = __floats2half2_rn(srow[0], srow[1]);
        h2[1] = __floats2half2_rn(srow[2], srow[3]);
        h2[2] = __floats2half2_rn(srow[4], srow[5]);
        h2[3] = __floats2half2_rn(srow[6], srow[7]);
        *(float4*)(ob + (size_t)r * CC + c8 * 8) = *(float4*)h2;
    }
}

// ---------------- launch -----------------------------------------------------
extern "C" void kernel_launch(void* const* d_in, const int* in_sizes, int n_in,
                              void* d_out, int out_size)
{
    const float* x    = (const float*)d_in[0];
    const float* ce   = (const float*)d_in[1];
    const int*   mask = (const int*)  d_in[2];
    const float* ln1g = (const float*)d_in[3];
    const float* ln1b = (const float*)d_in[4];
    const float* ln2g = (const float*)d_in[5];
    const float* ln2b = (const float*)d_in[6];
    const float* Wq   = (const float*)d_in[7];
    const float* bq   = (const float*)d_in[8];
    const float* Wk   = (const float*)d_in[9];
    const float* bk   = (const float*)d_in[10];
    const float* Wv   = (const float*)d_in[11];
    const float* bv   = (const float*)d_in[12];
    const float* Wp   = (const float*)d_in[13];
    const float* bp   = (const float*)d_in[14];
    const float* W1   = (const float*)d_in[15];
    const float* b1   = (const float*)d_in[16];
    const float* W2   = (const float*)d_in[17];
    const float* b2   = (const float*)d_in[18];
    float* out = (float*)d_out;

    float *p_xn, *p_x1, *p_bqkv;
    __half *p_tok, *p_qkv, *p_attn, *p_h2, *p_act, *p_wqkv, *p_wp, *p_w1, *p_w2;
    cudaGetSymbolAddress((void**)&p_xn,   g_xn);
    cudaGetSymbolAddress((void**)&p_tok,  g_tokens_h);
    cudaGetSymbolAddress((void**)&p_qkv,  g_qkv_h);
    cudaGetSymbolAddress((void**)&p_attn, g_attn_h);
    cudaGetSymbolAddress((void**)&p_x1,   g_x1);
    cudaGetSymbolAddress((void**)&p_h2,   g_h2_h);
    cudaGetSymbolAddress((void**)&p_act,  g_act_h);
    cudaGetSymbolAddress((void**)&p_wqkv, g_wqkv_h);
    cudaGetSymbolAddress((void**)&p_wp,   g_wp_h);
    cudaGetSymbolAddress((void**)&p_w1,   g_w1_h);
    cudaGetSymbolAddress((void**)&p_w2,   g_w2_h);
    cudaGetSymbolAddress((void**)&p_bqkv, g_bqkv);

    cudaFuncSetAttribute(gemm_h_kernel, cudaFuncAttributeMaxDynamicSharedMemorySize, GEMM_SMEM);
    cudaFuncSetAttribute(attn_kernel, cudaFuncAttributeMaxDynamicSharedMemorySize, ATTN_SMEM);

    int nCC = CC * CC, nCM = CC * MLPD;
    wpack_kernel<<<(nCC + 255) / 256, 256>>>(Wq, p_wqkv, CC, CC, QKVD, 0);
    wpack_kernel<<<(nCC + 255) / 256, 256>>>(Wk, p_wqkv, CC, CC, QKVD, CC);
    wpack_kernel<<<(nCC + 255) / 256, 256>>>(Wv, p_wqkv, CC, CC, QKVD, 2 * CC);
    wpack_kernel<<<(nCC + 255) / 256, 256>>>(Wp, p_wp, CC, CC, CC, 0);
    wpack_kernel<<<(nCM + 255) / 256, 256>>>(W1, p_w1, CC, MLPD, MLPD, 0);
    wpack_kernel<<<(nCM + 255) / 256, 256>>>(W2, p_w2, MLPD, CC, CC, 0);
    biaspack_kernel<<<(QKVD + 255) / 256, 256>>>(bq, bk, bv);

    mask_pack_kernel<<<(BB * NN * NW + 7) / 8, 256>>>(mask);
    ln1_concat_kernel<<<BB * TT, 256>>>(x, ce, ln1g, ln1b);

    // Q projection: only the B*N query rows (row-remapped into token space)
    gemm_h_kernel<<<dim3(BB * NN / 128, CC / 128), 256, GEMM_SMEM>>>(
        p_tok, p_wqkv, p_bqkv, nullptr, p_qkv, BB * NN, CC, CC, EPI_BIAS, 1,
        CC, QKVD, QKVD, 1);

    // K|V projection: all token rows, output columns CC..3CC
    gemm_h_kernel<<<dim3((MTOK + 127) / 128, (2 * CC) / 128), 256, GEMM_SMEM>>>(
        p_tok, p_wqkv + CC, p_bqkv + CC, nullptr, p_qkv + CC, MTOK, 2 * CC, CC,
        EPI_BIAS, 1, CC, QKVD, QKVD, 0);

    // attention (flash-2, fp16, O in registers)
    attn_kernel<<<dim3(NN / AQ, HH, BB), 256, ATTN_SMEM>>>();

    // proj + residual: x1 = xn + attn @ Wp + bp (fp32 out)
    gemm_h_kernel<<<dim3(BB * NN / 128, CC / 128), 256, GEMM_SMEM>>>(
        p_attn, p_wp, bp, p_xn, p_x1, BB * NN, CC, CC, EPI_ADD, 0,
        CC, CC, CC, 0);

    ln2_kernel<<<BB * NN, 256>>>(ln2g, ln2b);

    // MLP
    gemm_h_kernel<<<dim3(BB * NN / 128, MLPD / 128), 256, GEMM_SMEM>>>(
        p_h2, p_w1, b1, nullptr, p_act, BB * NN, MLPD, CC, EPI_GELU, 1,
        CC, MLPD, MLPD, 0);
    gemm_h_kernel<<<dim3(BB * NN / 128, CC / 128), 256, GEMM_SMEM>>>(
        p_act, p_w2, b2, p_x1, out, BB * NN, CC, MLPD, EPI_ADD, 0,
        MLPD, CC, CC, 0);
}